// round 11
// baseline (speedup 1.0000x reference)
#include <cuda_runtime.h>
#include <cuda_fp16.h>
#include <math.h>

#define NN 100000
#define EE 1600000

struct __align__(16) Rec {
    __half2 p01;   // dist(raw), a1
    __half2 p23;   // a2, a3
    int     col;
    int     pad;
};

// Scratch (device globals; no allocation allowed)
__device__ __half2 g_xwh[(size_t)NN * 32];  // fp16 xw: [node][32 x half2]
__device__ Rec    g_rec[EE];                // CSR-ordered 16B edge records
__device__ float4 g_pn[(size_t)NN * 2];     // packed {pos,0},{nrm,0} per node
__device__ int    g_deg[NN];
__device__ int    g_off[NN + 1];
__device__ int    g_cur[NN];
__device__ int    g_bsum[128];
__device__ double g_sum;

typedef unsigned long long u64;

__device__ __forceinline__ u64 ffma2(u64 a, u64 b, u64 c) {
    u64 d;
    asm("fma.rn.f32x2 %0, %1, %2, %3;" : "=l"(d) : "l"(a), "l"(b), "l"(c));
    return d;
}
__device__ __forceinline__ u64 pack2(float lo, float hi) {
    u64 r;
    asm("mov.b64 %0, {%1, %2};" : "=l"(r) : "f"(lo), "f"(hi));
    return r;
}
__device__ __forceinline__ float2 unpack2(u64 v) {
    float lo, hi;
    asm("mov.b64 {%0, %1}, %2;" : "=f"(lo), "=f"(hi) : "l"(v));
    return make_float2(lo, hi);
}
__device__ __forceinline__ unsigned int h2bits(__half2 h) {
    return *reinterpret_cast<unsigned int*>(&h);
}
__device__ __forceinline__ float2 bits2f2(unsigned int b) {
    __half2 h = *reinterpret_cast<__half2*>(&b);
    return __half22float2(h);
}

// ---------------------------------------------------------------- init: zero deg + pack pos/nrm + g_sum
__global__ void k_init(const float* __restrict__ pos, const float* __restrict__ nrm, int n) {
    int i = blockIdx.x * 256 + threadIdx.x;
    if (i < n) {
        g_deg[i] = 0;
        g_pn[2 * i + 0] = make_float4(pos[3 * i], pos[3 * i + 1], pos[3 * i + 2], 0.f);
        g_pn[2 * i + 1] = make_float4(nrm[3 * i], nrm[3 * i + 1], nrm[3 * i + 2], 0.f);
    }
    if (i == 0) g_sum = 0.0;
}

// ---------------------------------------------------------------- degree count
__global__ void k_prep(const int* __restrict__ ei, int E) {
    int e = blockIdx.x * 256 + threadIdx.x;
    if (e < E) atomicAdd(&g_deg[ei[e]], 1);
}

// ---------------------------------------------------------------- multi-block exclusive scan
__global__ void k_scan1(int n) {
    int base = blockIdx.x * 1024 + threadIdx.x * 4;
    int d0 = 0, d1 = 0, d2 = 0, d3 = 0;
    if (base + 3 < n) {
        int4 v = *(const int4*)&g_deg[base];
        d0 = v.x; d1 = v.y; d2 = v.z; d3 = v.w;
    } else {
        if (base + 0 < n) d0 = g_deg[base + 0];
        if (base + 1 < n) d1 = g_deg[base + 1];
        if (base + 2 < n) d2 = g_deg[base + 2];
        if (base + 3 < n) d3 = g_deg[base + 3];
    }
    int s = d0 + d1 + d2 + d3;
    int lane = threadIdx.x & 31, wid = threadIdx.x >> 5;
    int v = s;
#pragma unroll
    for (int o = 1; o < 32; o <<= 1) {
        int y = __shfl_up_sync(0xffffffffu, v, o);
        if (lane >= o) v += y;
    }
    __shared__ int ws[8];
    if (lane == 31) ws[wid] = v;
    __syncthreads();
    if (threadIdx.x == 0) {
        int run = 0;
#pragma unroll
        for (int i = 0; i < 8; i++) { int t = ws[i]; ws[i] = run; run += t; }
        g_bsum[blockIdx.x] = run;
    }
    __syncthreads();
    int excl = v - s + ws[wid];
    if (base + 0 < n) g_off[base + 0] = excl;
    if (base + 1 < n) g_off[base + 1] = excl + d0;
    if (base + 2 < n) g_off[base + 2] = excl + d0 + d1;
    if (base + 3 < n) g_off[base + 3] = excl + d0 + d1 + d2;
}

// ---------------------------------------------------------------- xw = x @ W1[:64,:] + b1 (fp16 store)
__global__ void __launch_bounds__(256) k_xw(const float* __restrict__ x,
                                            const float* __restrict__ W1,
                                            const float* __restrict__ b1, int n) {
    __shared__ float xs[32 * 132];
    __shared__ float ws[64 * 64];
    int n0 = blockIdx.x * 128;
    for (int i = threadIdx.x; i < 4096; i += 256) ws[i] = W1[i];

    int tx = threadIdx.x & 15, ty = threadIdx.x >> 4;
    float4 bq = *(const float4*)&b1[tx * 4];
    u64 acc[4][4];
#pragma unroll
    for (int j = 0; j < 4; j++) {
        acc[j][0] = pack2(bq.x, bq.x);
        acc[j][1] = pack2(bq.y, bq.y);
        acc[j][2] = pack2(bq.z, bq.z);
        acc[j][3] = pack2(bq.w, bq.w);
    }
    const float* xrow = &xs[ty * 8];
    const float* wrow = &ws[tx * 4];

#pragma unroll
    for (int pass = 0; pass < 2; pass++) {
        __syncthreads();
        for (int i = threadIdx.x; i < 128 * 8; i += 256) {
            int node = i >> 3, cq = (i & 7) * 4;
            float4 v = make_float4(0.f, 0.f, 0.f, 0.f);
            if (n0 + node < n)
                v = *(const float4*)&x[(size_t)(n0 + node) * 64 + pass * 32 + cq];
            xs[(cq + 0) * 132 + node] = v.x;
            xs[(cq + 1) * 132 + node] = v.y;
            xs[(cq + 2) * 132 + node] = v.z;
            xs[(cq + 3) * 132 + node] = v.w;
        }
        __syncthreads();
#pragma unroll 8
        for (int dd = 0; dd < 32; dd++) {
            int d = pass * 32 + dd;
            float4 a0 = *(const float4*)&xrow[dd * 132];
            float4 a1 = *(const float4*)&xrow[dd * 132 + 4];
            float4 w  = *(const float4*)&wrow[d * 64];
            u64 p0 = pack2(a0.x, a0.y);
            u64 p1 = pack2(a0.z, a0.w);
            u64 p2 = pack2(a1.x, a1.y);
            u64 p3 = pack2(a1.z, a1.w);
            u64 w0 = pack2(w.x, w.x), w1 = pack2(w.y, w.y);
            u64 w2 = pack2(w.z, w.z), w3 = pack2(w.w, w.w);
            acc[0][0] = ffma2(p0, w0, acc[0][0]); acc[0][1] = ffma2(p0, w1, acc[0][1]);
            acc[0][2] = ffma2(p0, w2, acc[0][2]); acc[0][3] = ffma2(p0, w3, acc[0][3]);
            acc[1][0] = ffma2(p1, w0, acc[1][0]); acc[1][1] = ffma2(p1, w1, acc[1][1]);
            acc[1][2] = ffma2(p1, w2, acc[1][2]); acc[1][3] = ffma2(p1, w3, acc[1][3]);
            acc[2][0] = ffma2(p2, w0, acc[2][0]); acc[2][1] = ffma2(p2, w1, acc[2][1]);
            acc[2][2] = ffma2(p2, w2, acc[2][2]); acc[2][3] = ffma2(p2, w3, acc[2][3]);
            acc[3][0] = ffma2(p3, w0, acc[3][0]); acc[3][1] = ffma2(p3, w1, acc[3][1]);
            acc[3][2] = ffma2(p3, w2, acc[3][2]); acc[3][3] = ffma2(p3, w3, acc[3][3]);
        }
    }
#pragma unroll
    for (int j = 0; j < 4; j++) {
        float2 c0 = unpack2(acc[j][0]);
        float2 c1 = unpack2(acc[j][1]);
        float2 c2 = unpack2(acc[j][2]);
        float2 c3 = unpack2(acc[j][3]);
        int ne = n0 + ty * 8 + 2 * j;
        if (ne < n) {
            __half2 hA = __floats2half2_rn(c0.x, c1.x);
            __half2 hB = __floats2half2_rn(c2.x, c3.x);
            *(uint2*)&g_xwh[(size_t)ne * 32 + tx * 2] = make_uint2(h2bits(hA), h2bits(hB));
        }
        if (ne + 1 < n) {
            __half2 hA = __floats2half2_rn(c0.y, c1.y);
            __half2 hB = __floats2half2_rn(c2.y, c3.y);
            *(uint2*)&g_xwh[(size_t)(ne + 1) * 32 + tx * 2] = make_uint2(h2bits(hA), h2bits(hB));
        }
    }
}

// Stage 2: scan block sums; g_off[n]=E.
__global__ void k_scan2(int nb, int n, int E) {
    int t = threadIdx.x;  // blockDim = 128
    int s = (t < nb) ? g_bsum[t] : 0;
    int lane = t & 31, wid = t >> 5;
    int v = s;
#pragma unroll
    for (int o = 1; o < 32; o <<= 1) {
        int y = __shfl_up_sync(0xffffffffu, v, o);
        if (lane >= o) v += y;
    }
    __shared__ int ws[4];
    if (lane == 31) ws[wid] = v;
    __syncthreads();
    if (t == 0) {
        int run = 0;
#pragma unroll
        for (int i = 0; i < 4; i++) { int x = ws[i]; ws[i] = run; run += x; }
    }
    __syncthreads();
    int excl = v - s + ws[wid];
    if (t < nb) g_bsum[t] = excl;
    if (t == 0) g_off[n] = E;
}

// Stage 3: add block offsets; init g_cur.
__global__ void k_scan3(int n) {
    int i = blockIdx.x * 256 + threadIdx.x;
    if (i >= n) return;
    int o = g_off[i] + g_bsum[i >> 10];
    g_off[i] = o;
    g_cur[i] = o;
}

// ---------------------------------------------------------------- ppf + scatter (16B recs) + dist sum
__device__ __forceinline__ float ppf_angle(float ax, float ay, float az,
                                           float bx, float by, float bz) {
    float cx = ay * bz - az * by;
    float cy = az * bx - ax * bz;
    float cz = ax * by - ay * bx;
    float dot = ax * bx + ay * by + az * bz;
    return atan2f(sqrtf(cx * cx + cy * cy + cz * cz), dot);
}

__global__ void k_scatter(const int* __restrict__ ei, int E) {
    int e = blockIdx.x * 256 + threadIdx.x;
    float dist = 0.f;
    if (e < E) {
        int r = ei[e], c = ei[E + e];
        float4 pr = g_pn[2 * r + 0];
        float4 n1 = g_pn[2 * r + 1];
        float4 pc = g_pn[2 * c + 0];
        float4 n2 = g_pn[2 * c + 1];
        float dx = pc.x - pr.x;
        float dy = pc.y - pr.y;
        float dz = pc.z - pr.z;
        dist = dx * dx + dy * dy + dz * dz;
        float a1 = ppf_angle(n1.x, n1.y, n1.z, dx, dy, dz);
        float a2 = ppf_angle(n2.x, n2.y, n2.z, dx, dy, dz);
        float a3 = ppf_angle(n1.x, n1.y, n1.z, n2.x, n2.y, n2.z);
        int p = atomicAdd(&g_cur[r], 1);
        __half2 h01 = __floats2half2_rn(dist, a1);   // raw dist; inv folded into w0 later
        __half2 h23 = __floats2half2_rn(a2, a3);
        int4 v = make_int4((int)h2bits(h01), (int)h2bits(h23), c, 0);
        *(int4*)&g_rec[p] = v;
    }
#pragma unroll
    for (int o = 16; o > 0; o >>= 1) dist += __shfl_down_sync(0xffffffffu, dist, o);
    __shared__ float wpart[8];
    int lane = threadIdx.x & 31, wid = threadIdx.x >> 5;
    if (lane == 0) wpart[wid] = dist;
    __syncthreads();
    if (threadIdx.x == 0) {
        float s = 0.f;
#pragma unroll
        for (int i = 0; i < 8; i++) s += wpart[i];
        atomicAdd(&g_sum, (double)s);
    }
}

// ---------------------------------------------------------------- fused: segmax (software-pipelined) + relu(seg @ W2 + b2)
__global__ void __launch_bounds__(256, 3) k_node_out(const float* __restrict__ W1,
                                                     const float* __restrict__ W2,
                                                     const float* __restrict__ b2,
                                                     float* __restrict__ out, int n, int E) {
    __shared__ float ws[64 * 128];
    __shared__ float sdup[8][4 * 128];   // [warp][node k][dup dims]
    for (int i = threadIdx.x; i < 64 * 128; i += 256) ws[i] = W2[i];
    __syncthreads();

    int lane = threadIdx.x & 31;
    int wid  = threadIdx.x >> 5;

    float inv = (float)((double)(E + n) / g_sum);
    const float* Wp = W1 + 64 * 64;
    float2 w0 = *(const float2*)&Wp[0 * 64 + lane * 2];
    w0.x *= inv; w0.y *= inv;                   // fold dist normalization into w0
    float2 w1 = *(const float2*)&Wp[1 * 64 + lane * 2];
    float2 w2 = *(const float2*)&Wp[2 * 64 + lane * 2];
    float2 w3 = *(const float2*)&Wp[3 * 64 + lane * 2];
    float4 bq = *(const float4*)&b2[lane * 4];
    u64 bb0 = pack2(bq.x, bq.y);
    u64 bb1 = pack2(bq.z, bq.w);

    const int4* rp = (const int4*)g_rec;

    int step = gridDim.x * 8 * 4;
    for (int base = (blockIdx.x * 8 + wid) * 4; base < n; base += step) {
#pragma unroll
        for (int k = 0; k < 4; k++) {
            int node = base + k;
            float ax = 0.f, ay = 0.f;
            if (node < n) {
                float2 xw = __half22float2(g_xwh[(size_t)node * 32 + lane]);
                ax = fmaxf(xw.x, 0.f);   // self-loop: ppf == 0 exactly
                ay = fmaxf(xw.y, 0.f);
                int beg = g_off[node];
                int end = g_off[node + 1];
                int nfull = (end - beg) >> 2;
                int i = beg;
                if (nfull >= 2) {
                    // 3-stage pipeline over 4-edge windows:
                    //   cur window (r*, x*) computing, next recs (s*) in flight.
                    int4 r0 = rp[i + 0], r1 = rp[i + 1], r2 = rp[i + 2], r3 = rp[i + 3];
                    int4 s0 = rp[i + 4], s1 = rp[i + 5], s2 = rp[i + 6], s3 = rp[i + 7];
                    i += 8;
                    float2 x0 = __half22float2(g_xwh[(size_t)r0.z * 32 + lane]);
                    float2 x1 = __half22float2(g_xwh[(size_t)r1.z * 32 + lane]);
                    float2 x2 = __half22float2(g_xwh[(size_t)r2.z * 32 + lane]);
                    float2 x3 = __half22float2(g_xwh[(size_t)r3.z * 32 + lane]);
                    for (int c = 0; c < nfull; c++) {
                        bool more = (c + 1 < nfull);
                        int4 t0, t1, t2, t3;
                        float2 y0, y1, y2, y3;
                        if (more) {
                            // promote prefetched recs, issue their gathers NOW
                            t0 = s0; t1 = s1; t2 = s2; t3 = s3;
                            y0 = __half22float2(g_xwh[(size_t)t0.z * 32 + lane]);
                            y1 = __half22float2(g_xwh[(size_t)t1.z * 32 + lane]);
                            y2 = __half22float2(g_xwh[(size_t)t2.z * 32 + lane]);
                            y3 = __half22float2(g_xwh[(size_t)t3.z * 32 + lane]);
                            if (c + 2 < nfull) {
                                s0 = rp[i + 0]; s1 = rp[i + 1];
                                s2 = rp[i + 2]; s3 = rp[i + 3];
                                i += 4;
                            }
                        }
                        // compute current window (loads above are in flight)
                        float2 pa0 = bits2f2((unsigned)r0.x), pb0 = bits2f2((unsigned)r0.y);
                        float2 pa1 = bits2f2((unsigned)r1.x), pb1 = bits2f2((unsigned)r1.y);
                        float2 pa2 = bits2f2((unsigned)r2.x), pb2 = bits2f2((unsigned)r2.y);
                        float2 pa3 = bits2f2((unsigned)r3.x), pb3 = bits2f2((unsigned)r3.y);
                        float hx0 = fmaf(pa0.x, w0.x, fmaf(pa0.y, w1.x, fmaf(pb0.x, w2.x, fmaf(pb0.y, w3.x, x0.x))));
                        float hy0 = fmaf(pa0.x, w0.y, fmaf(pa0.y, w1.y, fmaf(pb0.x, w2.y, fmaf(pb0.y, w3.y, x0.y))));
                        float hx1 = fmaf(pa1.x, w0.x, fmaf(pa1.y, w1.x, fmaf(pb1.x, w2.x, fmaf(pb1.y, w3.x, x1.x))));
                        float hy1 = fmaf(pa1.x, w0.y, fmaf(pa1.y, w1.y, fmaf(pb1.x, w2.y, fmaf(pb1.y, w3.y, x1.y))));
                        float hx2 = fmaf(pa2.x, w0.x, fmaf(pa2.y, w1.x, fmaf(pb2.x, w2.x, fmaf(pb2.y, w3.x, x2.x))));
                        float hy2 = fmaf(pa2.x, w0.y, fmaf(pa2.y, w1.y, fmaf(pb2.x, w2.y, fmaf(pb2.y, w3.y, x2.y))));
                        float hx3 = fmaf(pa3.x, w0.x, fmaf(pa3.y, w1.x, fmaf(pb3.x, w2.x, fmaf(pb3.y, w3.x, x3.x))));
                        float hy3 = fmaf(pa3.x, w0.y, fmaf(pa3.y, w1.y, fmaf(pb3.x, w2.y, fmaf(pb3.y, w3.y, x3.y))));
                        ax = fmaxf(ax, fmaxf(fmaxf(hx0, hx1), fmaxf(hx2, hx3)));
                        ay = fmaxf(ay, fmaxf(fmaxf(hy0, hy1), fmaxf(hy2, hy3)));
                        if (more) {
                            r0 = t0; r1 = t1; r2 = t2; r3 = t3;
                            x0 = y0; x1 = y1; x2 = y2; x3 = y3;
                        }
                    }
                    i = beg + (nfull << 2);
                } else if (nfull == 1) {
                    int4 v0 = rp[i + 0], v1 = rp[i + 1], v2 = rp[i + 2], v3 = rp[i + 3];
                    float2 xc0 = __half22float2(g_xwh[(size_t)v0.z * 32 + lane]);
                    float2 xc1 = __half22float2(g_xwh[(size_t)v1.z * 32 + lane]);
                    float2 xc2 = __half22float2(g_xwh[(size_t)v2.z * 32 + lane]);
                    float2 xc3 = __half22float2(g_xwh[(size_t)v3.z * 32 + lane]);
                    float2 pa0 = bits2f2((unsigned)v0.x), pb0 = bits2f2((unsigned)v0.y);
                    float2 pa1 = bits2f2((unsigned)v1.x), pb1 = bits2f2((unsigned)v1.y);
                    float2 pa2 = bits2f2((unsigned)v2.x), pb2 = bits2f2((unsigned)v2.y);
                    float2 pa3 = bits2f2((unsigned)v3.x), pb3 = bits2f2((unsigned)v3.y);
                    float hx0 = fmaf(pa0.x, w0.x, fmaf(pa0.y, w1.x, fmaf(pb0.x, w2.x, fmaf(pb0.y, w3.x, xc0.x))));
                    float hy0 = fmaf(pa0.x, w0.y, fmaf(pa0.y, w1.y, fmaf(pb0.x, w2.y, fmaf(pb0.y, w3.y, xc0.y))));
                    float hx1 = fmaf(pa1.x, w0.x, fmaf(pa1.y, w1.x, fmaf(pb1.x, w2.x, fmaf(pb1.y, w3.x, xc1.x))));
                    float hy1 = fmaf(pa1.x, w0.y, fmaf(pa1.y, w1.y, fmaf(pb1.x, w2.y, fmaf(pb1.y, w3.y, xc1.y))));
                    float hx2 = fmaf(pa2.x, w0.x, fmaf(pa2.y, w1.x, fmaf(pb2.x, w2.x, fmaf(pb2.y, w3.x, xc2.x))));
                    float hy2 = fmaf(pa2.x, w0.y, fmaf(pa2.y, w1.y, fmaf(pb2.x, w2.y, fmaf(pb2.y, w3.y, xc2.y))));
                    float hx3 = fmaf(pa3.x, w0.x, fmaf(pa3.y, w1.x, fmaf(pb3.x, w2.x, fmaf(pb3.y, w3.x, xc3.x))));
                    float hy3 = fmaf(pa3.x, w0.y, fmaf(pa3.y, w1.y, fmaf(pb3.x, w2.y, fmaf(pb3.y, w3.y, xc3.y))));
                    ax = fmaxf(ax, fmaxf(fmaxf(hx0, hx1), fmaxf(hx2, hx3)));
                    ay = fmaxf(ay, fmaxf(fmaxf(hy0, hy1), fmaxf(hy2, hy3)));
                    i += 4;
                }
                for (; i < end; i++) {
                    int4 v = rp[i];
                    float2 xc = __half22float2(g_xwh[(size_t)v.z * 32 + lane]);
                    float2 pa = bits2f2((unsigned)v.x), pb = bits2f2((unsigned)v.y);
                    float hx = fmaf(pa.x, w0.x, fmaf(pa.y, w1.x, fmaf(pb.x, w2.x, fmaf(pb.y, w3.x, xc.x))));
                    float hy = fmaf(pa.x, w0.y, fmaf(pa.y, w1.y, fmaf(pb.x, w2.y, fmaf(pb.y, w3.y, xc.y))));
                    ax = fmaxf(ax, hx);
                    ay = fmaxf(ay, hy);
                }
            }
            *(float4*)&sdup[wid][k * 128 + lane * 4] = make_float4(ax, ax, ay, ay);
        }
        __syncwarp();

        // phase 2: GEMV for 4 nodes with shared W2 reads + f32x2
        u64 a0x = bb0, a0y = bb1;
        u64 a1x = bb0, a1y = bb1;
        u64 a2x = bb0, a2y = bb1;
        u64 a3x = bb0, a3y = bb1;
#pragma unroll 8
        for (int jp = 0; jp < 32; jp++) {
            float4 wAf = *(const float4*)&ws[(2 * jp) * 128 + lane * 4];
            float4 wBf = *(const float4*)&ws[(2 * jp + 1) * 128 + lane * 4];
            float4 s0f = *(const float4*)&sdup[wid][0 * 128 + jp * 4];
            float4 s1f = *(const float4*)&sdup[wid][1 * 128 + jp * 4];
            float4 s2f = *(const float4*)&sdup[wid][2 * 128 + jp * 4];
            float4 s3f = *(const float4*)&sdup[wid][3 * 128 + jp * 4];
            u64 wAx = pack2(wAf.x, wAf.y), wAy = pack2(wAf.z, wAf.w);
            u64 wBx = pack2(wBf.x, wBf.y), wBy = pack2(wBf.z, wBf.w);
            u64 s0a = pack2(s0f.x, s0f.y), s0b = pack2(s0f.z, s0f.w);
            u64 s1a = pack2(s1f.x, s1f.y), s1b = pack2(s1f.z, s1f.w);
            u64 s2a = pack2(s2f.x, s2f.y), s2b = pack2(s2f.z, s2f.w);
            u64 s3a = pack2(s3f.x, s3f.y), s3b = pack2(s3f.z, s3f.w);
            a0x = ffma2(s0a, wAx, a0x); a0y = ffma2(s0a, wAy, a0y);
            a0x = ffma2(s0b, wBx, a0x); a0y = ffma2(s0b, wBy, a0y);
            a1x = ffma2(s1a, wAx, a1x); a1y = ffma2(s1a, wAy, a1y);
            a1x = ffma2(s1b, wBx, a1x); a1y = ffma2(s1b, wBy, a1y);
            a2x = ffma2(s2a, wAx, a2x); a2y = ffma2(s2a, wAy, a2y);
            a2x = ffma2(s2b, wBx, a2x); a2y = ffma2(s2b, wBy, a2y);
            a3x = ffma2(s3a, wAx, a3x); a3y = ffma2(s3a, wAy, a3y);
            a3x = ffma2(s3b, wBx, a3x); a3y = ffma2(s3b, wBy, a3y);
        }
        __syncwarp();

        u64 rx[4] = {a0x, a1x, a2x, a3x};
        u64 ry[4] = {a0y, a1y, a2y, a3y};
#pragma unroll
        for (int k = 0; k < 4; k++) {
            int node = base + k;
            if (node < n) {
                float2 lo = unpack2(rx[k]);
                float2 hi = unpack2(ry[k]);
                float4 o = make_float4(fmaxf(lo.x, 0.f), fmaxf(lo.y, 0.f),
                                       fmaxf(hi.x, 0.f), fmaxf(hi.y, 0.f));
                *(float4*)&out[(size_t)node * 128 + lane * 4] = o;
            }
        }
    }
}

// ---------------------------------------------------------------- launch
extern "C" void kernel_launch(void* const* d_in, const int* in_sizes, int n_in,
                              void* d_out, int out_size) {
    const float* x   = (const float*)d_in[0];
    const float* pos = (const float*)d_in[1];
    const float* nrm = (const float*)d_in[2];
    const int*   ei  = (const int*)d_in[3];
    // d_in[4] = batch (unused)
    const float* W1  = (const float*)d_in[5];
    const float* b1  = (const float*)d_in[6];
    const float* W2  = (const float*)d_in[7];
    const float* b2  = (const float*)d_in[8];
    float* out = (float*)d_out;

    int N = in_sizes[1] / 3;
    int E = in_sizes[3] / 2;
    int nb = (N + 1023) / 1024;

    k_init<<<(N + 255) / 256, 256>>>(pos, nrm, N);
    k_prep<<<(E + 255) / 256, 256>>>(ei, E);
    k_scan1<<<nb, 256>>>(N);
    k_xw<<<(N + 127) / 128, 256>>>(x, W1, b1, N);   // launch #4 -> profiled
    k_scan2<<<1, 128>>>(nb, N, E);
    k_scan3<<<(N + 255) / 256, 256>>>(N);
    k_scatter<<<(E + 255) / 256, 256>>>(ei, E);
    k_node_out<<<444, 256>>>(W1, W2, b2, out, N, E);
}

// round 12
// speedup vs baseline: 1.0294x; 1.0294x over previous
#include <cuda_runtime.h>
#include <cuda_fp16.h>
#include <math.h>

#define NN 100000
#define EE 1600000

struct __align__(16) Rec {
    __half2 p01;   // dist(raw), a1
    __half2 p23;   // a2, a3
    int     col;
    int     pad;
};

// Scratch (device globals; no allocation allowed)
__device__ __half2 g_xwh[(size_t)NN * 32];  // fp16 xw: [node][32 x half2]
__device__ Rec    g_rec[EE];                // CSR-ordered 16B edge records
__device__ float4 g_pn[(size_t)NN * 2];     // packed {pos,0},{nrm,0} per node
__device__ int    g_deg[NN];
__device__ int    g_off[NN + 1];
__device__ int    g_cur[NN];
__device__ int    g_bsum[128];
__device__ double g_sum;

typedef unsigned long long u64;

__device__ __forceinline__ u64 ffma2(u64 a, u64 b, u64 c) {
    u64 d;
    asm("fma.rn.f32x2 %0, %1, %2, %3;" : "=l"(d) : "l"(a), "l"(b), "l"(c));
    return d;
}
__device__ __forceinline__ u64 pack2(float lo, float hi) {
    u64 r;
    asm("mov.b64 %0, {%1, %2};" : "=l"(r) : "f"(lo), "f"(hi));
    return r;
}
__device__ __forceinline__ float2 unpack2(u64 v) {
    float lo, hi;
    asm("mov.b64 {%0, %1}, %2;" : "=f"(lo), "=f"(hi) : "l"(v));
    return make_float2(lo, hi);
}
__device__ __forceinline__ unsigned int h2bits(__half2 h) {
    return *reinterpret_cast<unsigned int*>(&h);
}
__device__ __forceinline__ float2 bits2f2(unsigned int b) {
    __half2 h = *reinterpret_cast<__half2*>(&b);
    return __half22float2(h);
}

// Fast atan2 for y >= 0 (result in [0, pi]). Minimax arctan poly, abs err ~1e-5 rad,
// far below the fp16 quantization the result passes through.
__device__ __forceinline__ float fast_atan2p(float y, float x) {
    float ax = fabsf(x);
    float mn = fminf(y, ax);
    float mx = fmaxf(y, ax);
    float t = __fdividef(mn, fmaxf(mx, 1e-30f));
    float z = t * t;
    float p = fmaf(z, -0.01172120f, 0.05265332f);
    p = fmaf(z, p, -0.11643287f);
    p = fmaf(z, p, 0.19354346f);
    p = fmaf(z, p, -0.33262347f);
    p = fmaf(z, p, 0.99997726f);
    float a = t * p;
    a = (y > ax) ? (1.57079632679f - a) : a;
    a = (x < 0.f) ? (3.14159265359f - a) : a;
    return a;
}

// ---------------------------------------------------------------- init: zero deg + pack pos/nrm + g_sum
__global__ void k_init(const float* __restrict__ pos, const float* __restrict__ nrm, int n) {
    int i = blockIdx.x * 256 + threadIdx.x;
    if (i < n) {
        g_deg[i] = 0;
        g_pn[2 * i + 0] = make_float4(pos[3 * i], pos[3 * i + 1], pos[3 * i + 2], 0.f);
        g_pn[2 * i + 1] = make_float4(nrm[3 * i], nrm[3 * i + 1], nrm[3 * i + 2], 0.f);
    }
    if (i == 0) g_sum = 0.0;
}

// ---------------------------------------------------------------- degree count
__global__ void k_prep(const int* __restrict__ ei, int E) {
    int e = blockIdx.x * 256 + threadIdx.x;
    if (e < E) atomicAdd(&g_deg[ei[e]], 1);
}

// ---------------------------------------------------------------- multi-block exclusive scan
__global__ void k_scan1(int n) {
    int base = blockIdx.x * 1024 + threadIdx.x * 4;
    int d0 = 0, d1 = 0, d2 = 0, d3 = 0;
    if (base + 3 < n) {
        int4 v = *(const int4*)&g_deg[base];
        d0 = v.x; d1 = v.y; d2 = v.z; d3 = v.w;
    } else {
        if (base + 0 < n) d0 = g_deg[base + 0];
        if (base + 1 < n) d1 = g_deg[base + 1];
        if (base + 2 < n) d2 = g_deg[base + 2];
        if (base + 3 < n) d3 = g_deg[base + 3];
    }
    int s = d0 + d1 + d2 + d3;
    int lane = threadIdx.x & 31, wid = threadIdx.x >> 5;
    int v = s;
#pragma unroll
    for (int o = 1; o < 32; o <<= 1) {
        int y = __shfl_up_sync(0xffffffffu, v, o);
        if (lane >= o) v += y;
    }
    __shared__ int ws[8];
    if (lane == 31) ws[wid] = v;
    __syncthreads();
    if (threadIdx.x == 0) {
        int run = 0;
#pragma unroll
        for (int i = 0; i < 8; i++) { int t = ws[i]; ws[i] = run; run += t; }
        g_bsum[blockIdx.x] = run;
    }
    __syncthreads();
    int excl = v - s + ws[wid];
    if (base + 0 < n) g_off[base + 0] = excl;
    if (base + 1 < n) g_off[base + 1] = excl + d0;
    if (base + 2 < n) g_off[base + 2] = excl + d0 + d1;
    if (base + 3 < n) g_off[base + 3] = excl + d0 + d1 + d2;
}

// ---------------------------------------------------------------- xw = x @ W1[:64,:] + b1 (fp16 store)
__global__ void __launch_bounds__(256) k_xw(const float* __restrict__ x,
                                            const float* __restrict__ W1,
                                            const float* __restrict__ b1, int n) {
    __shared__ float xs[32 * 132];
    __shared__ float ws[64 * 64];
    int n0 = blockIdx.x * 128;
    for (int i = threadIdx.x; i < 4096; i += 256) ws[i] = W1[i];

    int tx = threadIdx.x & 15, ty = threadIdx.x >> 4;
    float4 bq = *(const float4*)&b1[tx * 4];
    u64 acc[4][4];
#pragma unroll
    for (int j = 0; j < 4; j++) {
        acc[j][0] = pack2(bq.x, bq.x);
        acc[j][1] = pack2(bq.y, bq.y);
        acc[j][2] = pack2(bq.z, bq.z);
        acc[j][3] = pack2(bq.w, bq.w);
    }
    const float* xrow = &xs[ty * 8];
    const float* wrow = &ws[tx * 4];

#pragma unroll
    for (int pass = 0; pass < 2; pass++) {
        __syncthreads();
        for (int i = threadIdx.x; i < 128 * 8; i += 256) {
            int node = i >> 3, cq = (i & 7) * 4;
            float4 v = make_float4(0.f, 0.f, 0.f, 0.f);
            if (n0 + node < n)
                v = *(const float4*)&x[(size_t)(n0 + node) * 64 + pass * 32 + cq];
            xs[(cq + 0) * 132 + node] = v.x;
            xs[(cq + 1) * 132 + node] = v.y;
            xs[(cq + 2) * 132 + node] = v.z;
            xs[(cq + 3) * 132 + node] = v.w;
        }
        __syncthreads();
#pragma unroll 8
        for (int dd = 0; dd < 32; dd++) {
            int d = pass * 32 + dd;
            float4 a0 = *(const float4*)&xrow[dd * 132];
            float4 a1 = *(const float4*)&xrow[dd * 132 + 4];
            float4 w  = *(const float4*)&wrow[d * 64];
            u64 p0 = pack2(a0.x, a0.y);
            u64 p1 = pack2(a0.z, a0.w);
            u64 p2 = pack2(a1.x, a1.y);
            u64 p3 = pack2(a1.z, a1.w);
            u64 w0 = pack2(w.x, w.x), w1 = pack2(w.y, w.y);
            u64 w2 = pack2(w.z, w.z), w3 = pack2(w.w, w.w);
            acc[0][0] = ffma2(p0, w0, acc[0][0]); acc[0][1] = ffma2(p0, w1, acc[0][1]);
            acc[0][2] = ffma2(p0, w2, acc[0][2]); acc[0][3] = ffma2(p0, w3, acc[0][3]);
            acc[1][0] = ffma2(p1, w0, acc[1][0]); acc[1][1] = ffma2(p1, w1, acc[1][1]);
            acc[1][2] = ffma2(p1, w2, acc[1][2]); acc[1][3] = ffma2(p1, w3, acc[1][3]);
            acc[2][0] = ffma2(p2, w0, acc[2][0]); acc[2][1] = ffma2(p2, w1, acc[2][1]);
            acc[2][2] = ffma2(p2, w2, acc[2][2]); acc[2][3] = ffma2(p2, w3, acc[2][3]);
            acc[3][0] = ffma2(p3, w0, acc[3][0]); acc[3][1] = ffma2(p3, w1, acc[3][1]);
            acc[3][2] = ffma2(p3, w2, acc[3][2]); acc[3][3] = ffma2(p3, w3, acc[3][3]);
        }
    }
#pragma unroll
    for (int j = 0; j < 4; j++) {
        float2 c0 = unpack2(acc[j][0]);
        float2 c1 = unpack2(acc[j][1]);
        float2 c2 = unpack2(acc[j][2]);
        float2 c3 = unpack2(acc[j][3]);
        int ne = n0 + ty * 8 + 2 * j;
        if (ne < n) {
            __half2 hA = __floats2half2_rn(c0.x, c1.x);
            __half2 hB = __floats2half2_rn(c2.x, c3.x);
            *(uint2*)&g_xwh[(size_t)ne * 32 + tx * 2] = make_uint2(h2bits(hA), h2bits(hB));
        }
        if (ne + 1 < n) {
            __half2 hA = __floats2half2_rn(c0.y, c1.y);
            __half2 hB = __floats2half2_rn(c2.y, c3.y);
            *(uint2*)&g_xwh[(size_t)(ne + 1) * 32 + tx * 2] = make_uint2(h2bits(hA), h2bits(hB));
        }
    }
}

// Stage 2: scan block sums; g_off[n]=E.
__global__ void k_scan2(int nb, int n, int E) {
    int t = threadIdx.x;  // blockDim = 128
    int s = (t < nb) ? g_bsum[t] : 0;
    int lane = t & 31, wid = t >> 5;
    int v = s;
#pragma unroll
    for (int o = 1; o < 32; o <<= 1) {
        int y = __shfl_up_sync(0xffffffffu, v, o);
        if (lane >= o) v += y;
    }
    __shared__ int ws[4];
    if (lane == 31) ws[wid] = v;
    __syncthreads();
    if (t == 0) {
        int run = 0;
#pragma unroll
        for (int i = 0; i < 4; i++) { int x = ws[i]; ws[i] = run; run += x; }
    }
    __syncthreads();
    int excl = v - s + ws[wid];
    if (t < nb) g_bsum[t] = excl;
    if (t == 0) g_off[n] = E;
}

// Stage 3: add block offsets; init g_cur.
__global__ void k_scan3(int n) {
    int i = blockIdx.x * 256 + threadIdx.x;
    if (i >= n) return;
    int o = g_off[i] + g_bsum[i >> 10];
    g_off[i] = o;
    g_cur[i] = o;
}

// ---------------------------------------------------------------- ppf + scatter (16B recs) + dist sum
__device__ __forceinline__ float ppf_angle(float ax, float ay, float az,
                                           float bx, float by, float bz) {
    float cx = ay * bz - az * by;
    float cy = az * bx - ax * bz;
    float cz = ax * by - ay * bx;
    float dot = ax * bx + ay * by + az * bz;
    float nrm = sqrtf(cx * cx + cy * cy + cz * cz);
    return fast_atan2p(nrm, dot);
}

__global__ void k_scatter(const int* __restrict__ ei, int E) {
    int e = blockIdx.x * 256 + threadIdx.x;
    float dist = 0.f;
    if (e < E) {
        int r = ei[e], c = ei[E + e];
        float4 pr = g_pn[2 * r + 0];
        float4 n1 = g_pn[2 * r + 1];
        float4 pc = g_pn[2 * c + 0];
        float4 n2 = g_pn[2 * c + 1];
        float dx = pc.x - pr.x;
        float dy = pc.y - pr.y;
        float dz = pc.z - pr.z;
        dist = dx * dx + dy * dy + dz * dz;
        float a1 = ppf_angle(n1.x, n1.y, n1.z, dx, dy, dz);
        float a2 = ppf_angle(n2.x, n2.y, n2.z, dx, dy, dz);
        float a3 = ppf_angle(n1.x, n1.y, n1.z, n2.x, n2.y, n2.z);
        int p = atomicAdd(&g_cur[r], 1);
        __half2 h01 = __floats2half2_rn(dist, a1);   // raw dist; inv folded into w0 later
        __half2 h23 = __floats2half2_rn(a2, a3);
        int4 v = make_int4((int)h2bits(h01), (int)h2bits(h23), c, 0);
        *(int4*)&g_rec[p] = v;
    }
#pragma unroll
    for (int o = 16; o > 0; o >>= 1) dist += __shfl_down_sync(0xffffffffu, dist, o);
    __shared__ float wpart[8];
    int lane = threadIdx.x & 31, wid = threadIdx.x >> 5;
    if (lane == 0) wpart[wid] = dist;
    __syncthreads();
    if (threadIdx.x == 0) {
        float s = 0.f;
#pragma unroll
        for (int i = 0; i < 8; i++) s += wpart[i];
        atomicAdd(&g_sum, (double)s);
    }
}

// ---------------------------------------------------------------- fused: segmax (4 nodes/warp, unroll x4) + relu(seg @ W2 + b2)
__global__ void __launch_bounds__(256) k_node_out(const float* __restrict__ W1,
                                                  const float* __restrict__ W2,
                                                  const float* __restrict__ b2,
                                                  float* __restrict__ out, int n, int E) {
    __shared__ float ws[64 * 128];
    __shared__ float sdup[8][4 * 128];   // [warp][node k][dup dims]
    for (int i = threadIdx.x; i < 64 * 128; i += 256) ws[i] = W2[i];
    __syncthreads();

    int lane = threadIdx.x & 31;
    int wid  = threadIdx.x >> 5;

    float inv = (float)((double)(E + n) / g_sum);
    const float* Wp = W1 + 64 * 64;
    float2 w0 = *(const float2*)&Wp[0 * 64 + lane * 2];
    w0.x *= inv; w0.y *= inv;                   // fold dist normalization into w0
    float2 w1 = *(const float2*)&Wp[1 * 64 + lane * 2];
    float2 w2 = *(const float2*)&Wp[2 * 64 + lane * 2];
    float2 w3 = *(const float2*)&Wp[3 * 64 + lane * 2];
    float4 bq = *(const float4*)&b2[lane * 4];
    u64 bb0 = pack2(bq.x, bq.y);
    u64 bb1 = pack2(bq.z, bq.w);

    const int4* rp = (const int4*)g_rec;

    int step = gridDim.x * 8 * 4;
    for (int base = (blockIdx.x * 8 + wid) * 4; base < n; base += step) {
        // phase 1: segment-max for 4 consecutive nodes, edge loop unrolled x4
#pragma unroll
        for (int k = 0; k < 4; k++) {
            int node = base + k;
            float ax = 0.f, ay = 0.f;
            if (node < n) {
                float2 xw = __half22float2(g_xwh[(size_t)node * 32 + lane]);
                ax = fmaxf(xw.x, 0.f);   // self-loop: ppf == 0 exactly
                ay = fmaxf(xw.y, 0.f);
                int beg = g_off[node];
                int end = g_off[node + 1];
                int i = beg;
                for (; i + 3 < end; i += 4) {
                    int4 v0 = rp[i + 0];
                    int4 v1 = rp[i + 1];
                    int4 v2 = rp[i + 2];
                    int4 v3 = rp[i + 3];
                    float2 xc0 = __half22float2(g_xwh[(size_t)v0.z * 32 + lane]);
                    float2 xc1 = __half22float2(g_xwh[(size_t)v1.z * 32 + lane]);
                    float2 xc2 = __half22float2(g_xwh[(size_t)v2.z * 32 + lane]);
                    float2 xc3 = __half22float2(g_xwh[(size_t)v3.z * 32 + lane]);
                    float2 pa0 = bits2f2((unsigned)v0.x), pb0 = bits2f2((unsigned)v0.y);
                    float2 pa1 = bits2f2((unsigned)v1.x), pb1 = bits2f2((unsigned)v1.y);
                    float2 pa2 = bits2f2((unsigned)v2.x), pb2 = bits2f2((unsigned)v2.y);
                    float2 pa3 = bits2f2((unsigned)v3.x), pb3 = bits2f2((unsigned)v3.y);
                    float hx0 = fmaf(pa0.x, w0.x, fmaf(pa0.y, w1.x, fmaf(pb0.x, w2.x, fmaf(pb0.y, w3.x, xc0.x))));
                    float hy0 = fmaf(pa0.x, w0.y, fmaf(pa0.y, w1.y, fmaf(pb0.x, w2.y, fmaf(pb0.y, w3.y, xc0.y))));
                    float hx1 = fmaf(pa1.x, w0.x, fmaf(pa1.y, w1.x, fmaf(pb1.x, w2.x, fmaf(pb1.y, w3.x, xc1.x))));
                    float hy1 = fmaf(pa1.x, w0.y, fmaf(pa1.y, w1.y, fmaf(pb1.x, w2.y, fmaf(pb1.y, w3.y, xc1.y))));
                    float hx2 = fmaf(pa2.x, w0.x, fmaf(pa2.y, w1.x, fmaf(pb2.x, w2.x, fmaf(pb2.y, w3.x, xc2.x))));
                    float hy2 = fmaf(pa2.x, w0.y, fmaf(pa2.y, w1.y, fmaf(pb2.x, w2.y, fmaf(pb2.y, w3.y, xc2.y))));
                    float hx3 = fmaf(pa3.x, w0.x, fmaf(pa3.y, w1.x, fmaf(pb3.x, w2.x, fmaf(pb3.y, w3.x, xc3.x))));
                    float hy3 = fmaf(pa3.x, w0.y, fmaf(pa3.y, w1.y, fmaf(pb3.x, w2.y, fmaf(pb3.y, w3.y, xc3.y))));
                    ax = fmaxf(ax, fmaxf(fmaxf(hx0, hx1), fmaxf(hx2, hx3)));
                    ay = fmaxf(ay, fmaxf(fmaxf(hy0, hy1), fmaxf(hy2, hy3)));
                }
                for (; i < end; i++) {
                    int4 v = rp[i];
                    float2 xc = __half22float2(g_xwh[(size_t)v.z * 32 + lane]);
                    float2 pa = bits2f2((unsigned)v.x), pb = bits2f2((unsigned)v.y);
                    float hx = fmaf(pa.x, w0.x, fmaf(pa.y, w1.x, fmaf(pb.x, w2.x, fmaf(pb.y, w3.x, xc.x))));
                    float hy = fmaf(pa.x, w0.y, fmaf(pa.y, w1.y, fmaf(pb.x, w2.y, fmaf(pb.y, w3.y, xc.y))));
                    ax = fmaxf(ax, hx);
                    ay = fmaxf(ay, hy);
                }
            }
            *(float4*)&sdup[wid][k * 128 + lane * 4] = make_float4(ax, ax, ay, ay);
        }
        __syncwarp();

        // phase 2: GEMV for 4 nodes with shared W2 reads + f32x2
        u64 a0x = bb0, a0y = bb1;
        u64 a1x = bb0, a1y = bb1;
        u64 a2x = bb0, a2y = bb1;
        u64 a3x = bb0, a3y = bb1;
#pragma unroll 8
        for (int jp = 0; jp < 32; jp++) {
            float4 wAf = *(const float4*)&ws[(2 * jp) * 128 + lane * 4];
            float4 wBf = *(const float4*)&ws[(2 * jp + 1) * 128 + lane * 4];
            float4 s0f = *(const float4*)&sdup[wid][0 * 128 + jp * 4];
            float4 s1f = *(const float4*)&sdup[wid][1 * 128 + jp * 4];
            float4 s2f = *(const float4*)&sdup[wid][2 * 128 + jp * 4];
            float4 s3f = *(const float4*)&sdup[wid][3 * 128 + jp * 4];
            u64 wAx = pack2(wAf.x, wAf.y), wAy = pack2(wAf.z, wAf.w);
            u64 wBx = pack2(wBf.x, wBf.y), wBy = pack2(wBf.z, wBf.w);
            u64 s0a = pack2(s0f.x, s0f.y), s0b = pack2(s0f.z, s0f.w);
            u64 s1a = pack2(s1f.x, s1f.y), s1b = pack2(s1f.z, s1f.w);
            u64 s2a = pack2(s2f.x, s2f.y), s2b = pack2(s2f.z, s2f.w);
            u64 s3a = pack2(s3f.x, s3f.y), s3b = pack2(s3f.z, s3f.w);
            a0x = ffma2(s0a, wAx, a0x); a0y = ffma2(s0a, wAy, a0y);
            a0x = ffma2(s0b, wBx, a0x); a0y = ffma2(s0b, wBy, a0y);
            a1x = ffma2(s1a, wAx, a1x); a1y = ffma2(s1a, wAy, a1y);
            a1x = ffma2(s1b, wBx, a1x); a1y = ffma2(s1b, wBy, a1y);
            a2x = ffma2(s2a, wAx, a2x); a2y = ffma2(s2a, wAy, a2y);
            a2x = ffma2(s2b, wBx, a2x); a2y = ffma2(s2b, wBy, a2y);
            a3x = ffma2(s3a, wAx, a3x); a3y = ffma2(s3a, wAy, a3y);
            a3x = ffma2(s3b, wBx, a3x); a3y = ffma2(s3b, wBy, a3y);
        }
        __syncwarp();

        u64 rx[4] = {a0x, a1x, a2x, a3x};
        u64 ry[4] = {a0y, a1y, a2y, a3y};
#pragma unroll
        for (int k = 0; k < 4; k++) {
            int node = base + k;
            if (node < n) {
                float2 lo = unpack2(rx[k]);
                float2 hi = unpack2(ry[k]);
                float4 o = make_float4(fmaxf(lo.x, 0.f), fmaxf(lo.y, 0.f),
                                       fmaxf(hi.x, 0.f), fmaxf(hi.y, 0.f));
                *(float4*)&out[(size_t)node * 128 + lane * 4] = o;
            }
        }
    }
}

// ---------------------------------------------------------------- launch
extern "C" void kernel_launch(void* const* d_in, const int* in_sizes, int n_in,
                              void* d_out, int out_size) {
    const float* x   = (const float*)d_in[0];
    const float* pos = (const float*)d_in[1];
    const float* nrm = (const float*)d_in[2];
    const int*   ei  = (const int*)d_in[3];
    // d_in[4] = batch (unused)
    const float* W1  = (const float*)d_in[5];
    const float* b1  = (const float*)d_in[6];
    const float* W2  = (const float*)d_in[7];
    const float* b2  = (const float*)d_in[8];
    float* out = (float*)d_out;

    int N = in_sizes[1] / 3;
    int E = in_sizes[3] / 2;
    int nb = (N + 1023) / 1024;

    k_init<<<(N + 255) / 256, 256>>>(pos, nrm, N);
    k_prep<<<(E + 255) / 256, 256>>>(ei, E);
    k_scan1<<<nb, 256>>>(N);
    k_xw<<<(N + 127) / 128, 256>>>(x, W1, b1, N);   // launch #4 -> profiled
    k_scan2<<<1, 128>>>(nb, N, E);
    k_scan3<<<(N + 255) / 256, 256>>>(N);
    k_scatter<<<(E + 255) / 256, 256>>>(ei, E);
    k_node_out<<<592, 256>>>(W1, W2, b2, out, N, E);
}

// round 13
// speedup vs baseline: 1.0379x; 1.0083x over previous
#include <cuda_runtime.h>
#include <cuda_fp16.h>
#include <math.h>

#define NN 100000
#define EE 1600000

struct __align__(16) Rec {
    __half2 p01;   // dist(raw), a1
    __half2 p23;   // a2, a3
    int     col;
    int     pad;
};

// Scratch (device globals; no allocation allowed).
// INVARIANT: g_deg is all-zero and g_sum == 0.0 at every kernel_launch entry
// (zero-init at module load; re-established by k_node_out / k_scan23 each call).
__device__ __half2 g_xwh[(size_t)NN * 32];  // fp16 xw: [node][32 x half2]
__device__ Rec    g_rec[EE];                // CSR-ordered 16B edge records
__device__ float4 g_pn[(size_t)NN * 2];     // packed {pos,0},{nrm,0} per node
__device__ int    g_deg[NN];
__device__ int    g_off[NN + 1];
__device__ int    g_cur[NN];
__device__ int    g_bsum[128];
__device__ double g_sum;

typedef unsigned long long u64;

__device__ __forceinline__ u64 ffma2(u64 a, u64 b, u64 c) {
    u64 d;
    asm("fma.rn.f32x2 %0, %1, %2, %3;" : "=l"(d) : "l"(a), "l"(b), "l"(c));
    return d;
}
__device__ __forceinline__ u64 pack2(float lo, float hi) {
    u64 r;
    asm("mov.b64 %0, {%1, %2};" : "=l"(r) : "f"(lo), "f"(hi));
    return r;
}
__device__ __forceinline__ float2 unpack2(u64 v) {
    float lo, hi;
    asm("mov.b64 {%0, %1}, %2;" : "=f"(lo), "=f"(hi) : "l"(v));
    return make_float2(lo, hi);
}
__device__ __forceinline__ unsigned int h2bits(__half2 h) {
    return *reinterpret_cast<unsigned int*>(&h);
}
__device__ __forceinline__ float2 bits2f2(unsigned int b) {
    __half2 h = *reinterpret_cast<__half2*>(&b);
    return __half22float2(h);
}

__device__ __forceinline__ float fast_atan2p(float y, float x) {
    float ax = fabsf(x);
    float mn = fminf(y, ax);
    float mx = fmaxf(y, ax);
    float t = __fdividef(mn, fmaxf(mx, 1e-30f));
    float z = t * t;
    float p = fmaf(z, -0.01172120f, 0.05265332f);
    p = fmaf(z, p, -0.11643287f);
    p = fmaf(z, p, 0.19354346f);
    p = fmaf(z, p, -0.33262347f);
    p = fmaf(z, p, 0.99997726f);
    float a = t * p;
    a = (y > ax) ? (1.57079632679f - a) : a;
    a = (x < 0.f) ? (3.14159265359f - a) : a;
    return a;
}

// ---------------------------------------------------------------- prep: pack pos/nrm (e<N) + degree count (e<E)
// Relies on the g_deg==0 entry invariant.
__global__ void k_prep(const int* __restrict__ ei, const float* __restrict__ pos,
                       const float* __restrict__ nrm, int n, int E) {
    int e = blockIdx.x * 256 + threadIdx.x;
    if (e < n) {
        g_pn[2 * e + 0] = make_float4(pos[3 * e], pos[3 * e + 1], pos[3 * e + 2], 0.f);
        g_pn[2 * e + 1] = make_float4(nrm[3 * e], nrm[3 * e + 1], nrm[3 * e + 2], 0.f);
    }
    if (e < E) atomicAdd(&g_deg[ei[e]], 1);
}

// ---------------------------------------------------------------- scan stage 1
__global__ void k_scan1(int n) {
    int base = blockIdx.x * 1024 + threadIdx.x * 4;
    int d0 = 0, d1 = 0, d2 = 0, d3 = 0;
    if (base + 3 < n) {
        int4 v = *(const int4*)&g_deg[base];
        d0 = v.x; d1 = v.y; d2 = v.z; d3 = v.w;
    } else {
        if (base + 0 < n) d0 = g_deg[base + 0];
        if (base + 1 < n) d1 = g_deg[base + 1];
        if (base + 2 < n) d2 = g_deg[base + 2];
        if (base + 3 < n) d3 = g_deg[base + 3];
    }
    int s = d0 + d1 + d2 + d3;
    int lane = threadIdx.x & 31, wid = threadIdx.x >> 5;
    int v = s;
#pragma unroll
    for (int o = 1; o < 32; o <<= 1) {
        int y = __shfl_up_sync(0xffffffffu, v, o);
        if (lane >= o) v += y;
    }
    __shared__ int ws[8];
    if (lane == 31) ws[wid] = v;
    __syncthreads();
    if (threadIdx.x == 0) {
        int run = 0;
#pragma unroll
        for (int i = 0; i < 8; i++) { int t = ws[i]; ws[i] = run; run += t; }
        g_bsum[blockIdx.x] = run;
    }
    __syncthreads();
    int excl = v - s + ws[wid];
    if (base + 0 < n) g_off[base + 0] = excl;
    if (base + 1 < n) g_off[base + 1] = excl + d0;
    if (base + 2 < n) g_off[base + 2] = excl + d0 + d1;
    if (base + 3 < n) g_off[base + 3] = excl + d0 + d1 + d2;
}

// ---------------------------------------------------------------- scan stage 2+3 merged
// Each block redundantly scans the (<=128) block sums, then applies offsets.
__global__ void k_scan23(int nb, int n, int E) {
    __shared__ int bs[128];
    __shared__ int wsum[4];
    int t = threadIdx.x;  // 256 threads
    int s = 0, v = 0;
    int lane = t & 31, w = t >> 5;
    if (t < 128) {
        s = (t < nb) ? g_bsum[t] : 0;
        v = s;
#pragma unroll
        for (int o = 1; o < 32; o <<= 1) {
            int y = __shfl_up_sync(0xffffffffu, v, o);
            if (lane >= o) v += y;
        }
        if (lane == 31) wsum[w] = v;
    }
    __syncthreads();
    if (t == 0) {
        int run = 0;
#pragma unroll
        for (int i = 0; i < 4; i++) { int x = wsum[i]; wsum[i] = run; run += x; }
    }
    __syncthreads();
    if (t < 128) bs[t] = v - s + wsum[w];
    __syncthreads();
    int i = blockIdx.x * 256 + t;
    if (i < n) {
        int o = g_off[i] + bs[i >> 10];
        g_off[i] = o;
        g_cur[i] = o;
    }
    if (i == 0) {
        g_off[n] = E;
        g_sum = 0.0;   // reset accumulator before k_scatter adds to it
    }
}

// ---------------------------------------------------------------- ppf + scatter (16B recs) + dist sum   [profiled slot #4]
__device__ __forceinline__ float ppf_angle(float ax, float ay, float az,
                                           float bx, float by, float bz) {
    float cx = ay * bz - az * by;
    float cy = az * bx - ax * bz;
    float cz = ax * by - ay * bx;
    float dot = ax * bx + ay * by + az * bz;
    float nrm = sqrtf(cx * cx + cy * cy + cz * cz);
    return fast_atan2p(nrm, dot);
}

__global__ void k_scatter(const int* __restrict__ ei, int E) {
    int e = blockIdx.x * 256 + threadIdx.x;
    float dist = 0.f;
    if (e < E) {
        int r = ei[e], c = ei[E + e];
        float4 pr = g_pn[2 * r + 0];
        float4 n1 = g_pn[2 * r + 1];
        float4 pc = g_pn[2 * c + 0];
        float4 n2 = g_pn[2 * c + 1];
        float dx = pc.x - pr.x;
        float dy = pc.y - pr.y;
        float dz = pc.z - pr.z;
        dist = dx * dx + dy * dy + dz * dz;
        float a1 = ppf_angle(n1.x, n1.y, n1.z, dx, dy, dz);
        float a2 = ppf_angle(n2.x, n2.y, n2.z, dx, dy, dz);
        float a3 = ppf_angle(n1.x, n1.y, n1.z, n2.x, n2.y, n2.z);
        int p = atomicAdd(&g_cur[r], 1);
        __half2 h01 = __floats2half2_rn(dist, a1);   // raw dist; inv folded into w0 later
        __half2 h23 = __floats2half2_rn(a2, a3);
        int4 v = make_int4((int)h2bits(h01), (int)h2bits(h23), c, 0);
        *(int4*)&g_rec[p] = v;
    }
#pragma unroll
    for (int o = 16; o > 0; o >>= 1) dist += __shfl_down_sync(0xffffffffu, dist, o);
    __shared__ float wpart[8];
    int lane = threadIdx.x & 31, wid = threadIdx.x >> 5;
    if (lane == 0) wpart[wid] = dist;
    __syncthreads();
    if (threadIdx.x == 0) {
        float s = 0.f;
#pragma unroll
        for (int i = 0; i < 8; i++) s += wpart[i];
        atomicAdd(&g_sum, (double)s);
    }
}

// ---------------------------------------------------------------- xw = x @ W1[:64,:] + b1 (fp16 store)
__global__ void __launch_bounds__(256) k_xw(const float* __restrict__ x,
                                            const float* __restrict__ W1,
                                            const float* __restrict__ b1, int n) {
    __shared__ float xs[32 * 132];
    __shared__ float ws[64 * 64];
    int n0 = blockIdx.x * 128;
    for (int i = threadIdx.x; i < 4096; i += 256) ws[i] = W1[i];

    int tx = threadIdx.x & 15, ty = threadIdx.x >> 4;
    float4 bq = *(const float4*)&b1[tx * 4];
    u64 acc[4][4];
#pragma unroll
    for (int j = 0; j < 4; j++) {
        acc[j][0] = pack2(bq.x, bq.x);
        acc[j][1] = pack2(bq.y, bq.y);
        acc[j][2] = pack2(bq.z, bq.z);
        acc[j][3] = pack2(bq.w, bq.w);
    }
    const float* xrow = &xs[ty * 8];
    const float* wrow = &ws[tx * 4];

#pragma unroll
    for (int pass = 0; pass < 2; pass++) {
        __syncthreads();
        for (int i = threadIdx.x; i < 128 * 8; i += 256) {
            int node = i >> 3, cq = (i & 7) * 4;
            float4 v = make_float4(0.f, 0.f, 0.f, 0.f);
            if (n0 + node < n)
                v = *(const float4*)&x[(size_t)(n0 + node) * 64 + pass * 32 + cq];
            xs[(cq + 0) * 132 + node] = v.x;
            xs[(cq + 1) * 132 + node] = v.y;
            xs[(cq + 2) * 132 + node] = v.z;
            xs[(cq + 3) * 132 + node] = v.w;
        }
        __syncthreads();
#pragma unroll 8
        for (int dd = 0; dd < 32; dd++) {
            int d = pass * 32 + dd;
            float4 a0 = *(const float4*)&xrow[dd * 132];
            float4 a1 = *(const float4*)&xrow[dd * 132 + 4];
            float4 w  = *(const float4*)&wrow[d * 64];
            u64 p0 = pack2(a0.x, a0.y);
            u64 p1 = pack2(a0.z, a0.w);
            u64 p2 = pack2(a1.x, a1.y);
            u64 p3 = pack2(a1.z, a1.w);
            u64 w0 = pack2(w.x, w.x), w1 = pack2(w.y, w.y);
            u64 w2 = pack2(w.z, w.z), w3 = pack2(w.w, w.w);
            acc[0][0] = ffma2(p0, w0, acc[0][0]); acc[0][1] = ffma2(p0, w1, acc[0][1]);
            acc[0][2] = ffma2(p0, w2, acc[0][2]); acc[0][3] = ffma2(p0, w3, acc[0][3]);
            acc[1][0] = ffma2(p1, w0, acc[1][0]); acc[1][1] = ffma2(p1, w1, acc[1][1]);
            acc[1][2] = ffma2(p1, w2, acc[1][2]); acc[1][3] = ffma2(p1, w3, acc[1][3]);
            acc[2][0] = ffma2(p2, w0, acc[2][0]); acc[2][1] = ffma2(p2, w1, acc[2][1]);
            acc[2][2] = ffma2(p2, w2, acc[2][2]); acc[2][3] = ffma2(p2, w3, acc[2][3]);
            acc[3][0] = ffma2(p3, w0, acc[3][0]); acc[3][1] = ffma2(p3, w1, acc[3][1]);
            acc[3][2] = ffma2(p3, w2, acc[3][2]); acc[3][3] = ffma2(p3, w3, acc[3][3]);
        }
    }
#pragma unroll
    for (int j = 0; j < 4; j++) {
        float2 c0 = unpack2(acc[j][0]);
        float2 c1 = unpack2(acc[j][1]);
        float2 c2 = unpack2(acc[j][2]);
        float2 c3 = unpack2(acc[j][3]);
        int ne = n0 + ty * 8 + 2 * j;
        if (ne < n) {
            __half2 hA = __floats2half2_rn(c0.x, c1.x);
            __half2 hB = __floats2half2_rn(c2.x, c3.x);
            *(uint2*)&g_xwh[(size_t)ne * 32 + tx * 2] = make_uint2(h2bits(hA), h2bits(hB));
        }
        if (ne + 1 < n) {
            __half2 hA = __floats2half2_rn(c0.y, c1.y);
            __half2 hB = __floats2half2_rn(c2.y, c3.y);
            *(uint2*)&g_xwh[(size_t)(ne + 1) * 32 + tx * 2] = make_uint2(h2bits(hA), h2bits(hB));
        }
    }
}

// ---------------------------------------------------------------- fused: segmax + relu(seg @ W2 + b2); re-zeroes g_deg at tail
__global__ void __launch_bounds__(256) k_node_out(const float* __restrict__ W1,
                                                  const float* __restrict__ W2,
                                                  const float* __restrict__ b2,
                                                  float* __restrict__ out, int n, int E) {
    __shared__ float ws[64 * 128];
    __shared__ float sdup[8][4 * 128];   // [warp][node k][dup dims]
    for (int i = threadIdx.x; i < 64 * 128; i += 256) ws[i] = W2[i];
    __syncthreads();

    int lane = threadIdx.x & 31;
    int wid  = threadIdx.x >> 5;

    float inv = (float)((double)(E + n) / g_sum);
    const float* Wp = W1 + 64 * 64;
    float2 w0 = *(const float2*)&Wp[0 * 64 + lane * 2];
    w0.x *= inv; w0.y *= inv;                   // fold dist normalization into w0
    float2 w1 = *(const float2*)&Wp[1 * 64 + lane * 2];
    float2 w2 = *(const float2*)&Wp[2 * 64 + lane * 2];
    float2 w3 = *(const float2*)&Wp[3 * 64 + lane * 2];
    float4 bq = *(const float4*)&b2[lane * 4];
    u64 bb0 = pack2(bq.x, bq.y);
    u64 bb1 = pack2(bq.z, bq.w);

    const int4* rp = (const int4*)g_rec;

    int step = gridDim.x * 8 * 4;
    for (int base = (blockIdx.x * 8 + wid) * 4; base < n; base += step) {
        // phase 1: segment-max for 4 consecutive nodes, edge loop unrolled x4
#pragma unroll
        for (int k = 0; k < 4; k++) {
            int node = base + k;
            float ax = 0.f, ay = 0.f;
            if (node < n) {
                float2 xw = __half22float2(g_xwh[(size_t)node * 32 + lane]);
                ax = fmaxf(xw.x, 0.f);   // self-loop: ppf == 0 exactly
                ay = fmaxf(xw.y, 0.f);
                int beg = g_off[node];
                int end = g_off[node + 1];
                int i = beg;
                for (; i + 3 < end; i += 4) {
                    int4 v0 = rp[i + 0];
                    int4 v1 = rp[i + 1];
                    int4 v2 = rp[i + 2];
                    int4 v3 = rp[i + 3];
                    float2 xc0 = __half22float2(g_xwh[(size_t)v0.z * 32 + lane]);
                    float2 xc1 = __half22float2(g_xwh[(size_t)v1.z * 32 + lane]);
                    float2 xc2 = __half22float2(g_xwh[(size_t)v2.z * 32 + lane]);
                    float2 xc3 = __half22float2(g_xwh[(size_t)v3.z * 32 + lane]);
                    float2 pa0 = bits2f2((unsigned)v0.x), pb0 = bits2f2((unsigned)v0.y);
                    float2 pa1 = bits2f2((unsigned)v1.x), pb1 = bits2f2((unsigned)v1.y);
                    float2 pa2 = bits2f2((unsigned)v2.x), pb2 = bits2f2((unsigned)v2.y);
                    float2 pa3 = bits2f2((unsigned)v3.x), pb3 = bits2f2((unsigned)v3.y);
                    float hx0 = fmaf(pa0.x, w0.x, fmaf(pa0.y, w1.x, fmaf(pb0.x, w2.x, fmaf(pb0.y, w3.x, xc0.x))));
                    float hy0 = fmaf(pa0.x, w0.y, fmaf(pa0.y, w1.y, fmaf(pb0.x, w2.y, fmaf(pb0.y, w3.y, xc0.y))));
                    float hx1 = fmaf(pa1.x, w0.x, fmaf(pa1.y, w1.x, fmaf(pb1.x, w2.x, fmaf(pb1.y, w3.x, xc1.x))));
                    float hy1 = fmaf(pa1.x, w0.y, fmaf(pa1.y, w1.y, fmaf(pb1.x, w2.y, fmaf(pb1.y, w3.y, xc1.y))));
                    float hx2 = fmaf(pa2.x, w0.x, fmaf(pa2.y, w1.x, fmaf(pb2.x, w2.x, fmaf(pb2.y, w3.x, xc2.x))));
                    float hy2 = fmaf(pa2.x, w0.y, fmaf(pa2.y, w1.y, fmaf(pb2.x, w2.y, fmaf(pb2.y, w3.y, xc2.y))));
                    float hx3 = fmaf(pa3.x, w0.x, fmaf(pa3.y, w1.x, fmaf(pb3.x, w2.x, fmaf(pb3.y, w3.x, xc3.x))));
                    float hy3 = fmaf(pa3.x, w0.y, fmaf(pa3.y, w1.y, fmaf(pb3.x, w2.y, fmaf(pb3.y, w3.y, xc3.y))));
                    ax = fmaxf(ax, fmaxf(fmaxf(hx0, hx1), fmaxf(hx2, hx3)));
                    ay = fmaxf(ay, fmaxf(fmaxf(hy0, hy1), fmaxf(hy2, hy3)));
                }
                for (; i < end; i++) {
                    int4 v = rp[i];
                    float2 xc = __half22float2(g_xwh[(size_t)v.z * 32 + lane]);
                    float2 pa = bits2f2((unsigned)v.x), pb = bits2f2((unsigned)v.y);
                    float hx = fmaf(pa.x, w0.x, fmaf(pa.y, w1.x, fmaf(pb.x, w2.x, fmaf(pb.y, w3.x, xc.x))));
                    float hy = fmaf(pa.x, w0.y, fmaf(pa.y, w1.y, fmaf(pb.x, w2.y, fmaf(pb.y, w3.y, xc.y))));
                    ax = fmaxf(ax, hx);
                    ay = fmaxf(ay, hy);
                }
            }
            *(float4*)&sdup[wid][k * 128 + lane * 4] = make_float4(ax, ax, ay, ay);
        }
        __syncwarp();

        // phase 2: GEMV for 4 nodes; DIRECT u64 smem loads (adjacent floats = f32x2 pairs)
        u64 a0x = bb0, a0y = bb1;
        u64 a1x = bb0, a1y = bb1;
        u64 a2x = bb0, a2y = bb1;
        u64 a3x = bb0, a3y = bb1;
#pragma unroll 8
        for (int jp = 0; jp < 32; jp++) {
            ulonglong2 wA = *(const ulonglong2*)&ws[(2 * jp) * 128 + lane * 4];
            ulonglong2 wB = *(const ulonglong2*)&ws[(2 * jp + 1) * 128 + lane * 4];
            ulonglong2 s0 = *(const ulonglong2*)&sdup[wid][0 * 128 + jp * 4];
            ulonglong2 s1 = *(const ulonglong2*)&sdup[wid][1 * 128 + jp * 4];
            ulonglong2 s2 = *(const ulonglong2*)&sdup[wid][2 * 128 + jp * 4];
            ulonglong2 s3 = *(const ulonglong2*)&sdup[wid][3 * 128 + jp * 4];
            a0x = ffma2(s0.x, wA.x, a0x); a0y = ffma2(s0.x, wA.y, a0y);
            a0x = ffma2(s0.y, wB.x, a0x); a0y = ffma2(s0.y, wB.y, a0y);
            a1x = ffma2(s1.x, wA.x, a1x); a1y = ffma2(s1.x, wA.y, a1y);
            a1x = ffma2(s1.y, wB.x, a1x); a1y = ffma2(s1.y, wB.y, a1y);
            a2x = ffma2(s2.x, wA.x, a2x); a2y = ffma2(s2.x, wA.y, a2y);
            a2x = ffma2(s2.y, wB.x, a2x); a2y = ffma2(s2.y, wB.y, a2y);
            a3x = ffma2(s3.x, wA.x, a3x); a3y = ffma2(s3.x, wA.y, a3y);
            a3x = ffma2(s3.y, wB.x, a3x); a3y = ffma2(s3.y, wB.y, a3y);
        }
        __syncwarp();

        u64 rx[4] = {a0x, a1x, a2x, a3x};
        u64 ry[4] = {a0y, a1y, a2y, a3y};
#pragma unroll
        for (int k = 0; k < 4; k++) {
            int node = base + k;
            if (node < n) {
                float2 lo = unpack2(rx[k]);
                float2 hi = unpack2(ry[k]);
                float4 o = make_float4(fmaxf(lo.x, 0.f), fmaxf(lo.y, 0.f),
                                       fmaxf(hi.x, 0.f), fmaxf(hi.y, 0.f));
                *(float4*)&out[(size_t)node * 128 + lane * 4] = o;
            }
        }
    }

    // tail: re-zero g_deg for the next kernel_launch call (entry invariant)
    for (int i = blockIdx.x * 256 + threadIdx.x; i < n; i += gridDim.x * 256)
        g_deg[i] = 0;
}

// ---------------------------------------------------------------- launch (6 kernels)
extern "C" void kernel_launch(void* const* d_in, const int* in_sizes, int n_in,
                              void* d_out, int out_size) {
    const float* x   = (const float*)d_in[0];
    const float* pos = (const float*)d_in[1];
    const float* nrm = (const float*)d_in[2];
    const int*   ei  = (const int*)d_in[3];
    // d_in[4] = batch (unused)
    const float* W1  = (const float*)d_in[5];
    const float* b1  = (const float*)d_in[6];
    const float* W2  = (const float*)d_in[7];
    const float* b2  = (const float*)d_in[8];
    float* out = (float*)d_out;

    int N = in_sizes[1] / 3;
    int E = in_sizes[3] / 2;
    int nb = (N + 1023) / 1024;

    k_prep<<<(E + 255) / 256, 256>>>(ei, pos, nrm, N, E);
    k_scan1<<<nb, 256>>>(N);
    k_scan23<<<(N + 255) / 256, 256>>>(nb, N, E);
    k_scatter<<<(E + 255) / 256, 256>>>(ei, E);            // profiled slot #4
    k_xw<<<(N + 127) / 128, 256>>>(x, W1, b1, N);
    k_node_out<<<592, 256>>>(W1, W2, b2, out, N, E);
}

// round 14
// speedup vs baseline: 1.0591x; 1.0203x over previous
#include <cuda_runtime.h>
#include <cuda_fp16.h>
#include <math.h>

#define NN 100000
#define EE 1600000

// Scratch (device globals; no allocation allowed).
// INVARIANT: g_deg all-zero at every kernel_launch entry (zero-init at load;
// re-established by k_node_out tail each call). g_sum is reset in k_scan23.
__device__ __half2 g_xwh[(size_t)NN * 32];  // fp16 xw: [node][32 x half2]
__device__ int    g_col[EE];                // CSR-ordered target cols
__device__ float4 g_pn[(size_t)NN * 2];     // packed {pos,0},{nrm,0} per node
__device__ int    g_deg[NN];
__device__ int    g_off[NN + 1];
__device__ int    g_cur[NN];
__device__ int    g_bsum[128];
__device__ double g_sum;

typedef unsigned long long u64;

__device__ __forceinline__ u64 ffma2(u64 a, u64 b, u64 c) {
    u64 d;
    asm("fma.rn.f32x2 %0, %1, %2, %3;" : "=l"(d) : "l"(a), "l"(b), "l"(c));
    return d;
}
__device__ __forceinline__ u64 pack2(float lo, float hi) {
    u64 r;
    asm("mov.b64 %0, {%1, %2};" : "=l"(r) : "f"(lo), "f"(hi));
    return r;
}
__device__ __forceinline__ float2 unpack2(u64 v) {
    float lo, hi;
    asm("mov.b64 {%0, %1}, %2;" : "=f"(lo), "=f"(hi) : "l"(v));
    return make_float2(lo, hi);
}

__device__ __forceinline__ float fast_atan2p(float y, float x) {
    float ax = fabsf(x);
    float mn = fminf(y, ax);
    float mx = fmaxf(y, ax);
    float t = __fdividef(mn, fmaxf(mx, 1e-30f));
    float z = t * t;
    float p = fmaf(z, -0.01172120f, 0.05265332f);
    p = fmaf(z, p, -0.11643287f);
    p = fmaf(z, p, 0.19354346f);
    p = fmaf(z, p, -0.33262347f);
    p = fmaf(z, p, 0.99997726f);
    float a = t * p;
    a = (y > ax) ? (1.57079632679f - a) : a;
    a = (x < 0.f) ? (3.14159265359f - a) : a;
    return a;
}

__device__ __forceinline__ float ppf_angle(float ax, float ay, float az,
                                           float bx, float by, float bz) {
    float cx = ay * bz - az * by;
    float cy = az * bx - ax * bz;
    float cz = ax * by - ay * bx;
    float dot = ax * bx + ay * by + az * bz;
    float nrm = sqrtf(cx * cx + cy * cy + cz * cz);
    return fast_atan2p(nrm, dot);
}

// ---------------------------------------------------------------- prep: pack pos/nrm (e<N) + degree count (e<E)
__global__ void k_prep(const int* __restrict__ ei, const float* __restrict__ pos,
                       const float* __restrict__ nrm, int n, int E) {
    int e = blockIdx.x * 256 + threadIdx.x;
    if (e < n) {
        g_pn[2 * e + 0] = make_float4(pos[3 * e], pos[3 * e + 1], pos[3 * e + 2], 0.f);
        g_pn[2 * e + 1] = make_float4(nrm[3 * e], nrm[3 * e + 1], nrm[3 * e + 2], 0.f);
    }
    if (e < E) atomicAdd(&g_deg[ei[e]], 1);
}

// ---------------------------------------------------------------- scan stage 1
__global__ void k_scan1(int n) {
    int base = blockIdx.x * 1024 + threadIdx.x * 4;
    int d0 = 0, d1 = 0, d2 = 0, d3 = 0;
    if (base + 3 < n) {
        int4 v = *(const int4*)&g_deg[base];
        d0 = v.x; d1 = v.y; d2 = v.z; d3 = v.w;
    } else {
        if (base + 0 < n) d0 = g_deg[base + 0];
        if (base + 1 < n) d1 = g_deg[base + 1];
        if (base + 2 < n) d2 = g_deg[base + 2];
        if (base + 3 < n) d3 = g_deg[base + 3];
    }
    int s = d0 + d1 + d2 + d3;
    int lane = threadIdx.x & 31, wid = threadIdx.x >> 5;
    int v = s;
#pragma unroll
    for (int o = 1; o < 32; o <<= 1) {
        int y = __shfl_up_sync(0xffffffffu, v, o);
        if (lane >= o) v += y;
    }
    __shared__ int ws[8];
    if (lane == 31) ws[wid] = v;
    __syncthreads();
    if (threadIdx.x == 0) {
        int run = 0;
#pragma unroll
        for (int i = 0; i < 8; i++) { int t = ws[i]; ws[i] = run; run += t; }
        g_bsum[blockIdx.x] = run;
    }
    __syncthreads();
    int excl = v - s + ws[wid];
    if (base + 0 < n) g_off[base + 0] = excl;
    if (base + 1 < n) g_off[base + 1] = excl + d0;
    if (base + 2 < n) g_off[base + 2] = excl + d0 + d1;
    if (base + 3 < n) g_off[base + 3] = excl + d0 + d1 + d2;
}

// ---------------------------------------------------------------- scan stage 2+3 merged (also resets g_sum)
__global__ void k_scan23(int nb, int n, int E) {
    __shared__ int bs[128];
    __shared__ int wsum[4];
    int t = threadIdx.x;  // 256 threads
    int s = 0, v = 0;
    int lane = t & 31, w = t >> 5;
    if (t < 128) {
        s = (t < nb) ? g_bsum[t] : 0;
        v = s;
#pragma unroll
        for (int o = 1; o < 32; o <<= 1) {
            int y = __shfl_up_sync(0xffffffffu, v, o);
            if (lane >= o) v += y;
        }
        if (lane == 31) wsum[w] = v;
    }
    __syncthreads();
    if (t == 0) {
        int run = 0;
#pragma unroll
        for (int i = 0; i < 4; i++) { int x = wsum[i]; wsum[i] = run; run += x; }
    }
    __syncthreads();
    if (t < 128) bs[t] = v - s + wsum[w];
    __syncthreads();
    int i = blockIdx.x * 256 + t;
    if (i < n) {
        int o = g_off[i] + bs[i >> 10];
        g_off[i] = o;
        g_cur[i] = o;
    }
    if (i == 0) {
        g_off[n] = E;
        g_sum = 0.0;   // reset accumulator before k_scat1 adds to it
    }
}

// ---------------------------------------------------------------- col-scatter + dist sum   [profiled slot #4]
__global__ void k_scat1(const int* __restrict__ ei, int E) {
    int e = blockIdx.x * 256 + threadIdx.x;
    float dist = 0.f;
    if (e < E) {
        int r = ei[e], c = ei[E + e];
        float4 pr = g_pn[2 * r + 0];
        float4 pc = g_pn[2 * c + 0];
        float dx = pc.x - pr.x;
        float dy = pc.y - pr.y;
        float dz = pc.z - pr.z;
        dist = dx * dx + dy * dy + dz * dz;
        int p = atomicAdd(&g_cur[r], 1);
        g_col[p] = c;
    }
#pragma unroll
    for (int o = 16; o > 0; o >>= 1) dist += __shfl_down_sync(0xffffffffu, dist, o);
    __shared__ float wpart[8];
    int lane = threadIdx.x & 31, wid = threadIdx.x >> 5;
    if (lane == 0) wpart[wid] = dist;
    __syncthreads();
    if (threadIdx.x == 0) {
        float s = 0.f;
#pragma unroll
        for (int i = 0; i < 8; i++) s += wpart[i];
        atomicAdd(&g_sum, (double)s);
    }
}

// ---------------------------------------------------------------- xw = x @ W1[:64,:] + b1 (fp16 store)
__global__ void __launch_bounds__(256) k_xw(const float* __restrict__ x,
                                            const float* __restrict__ W1,
                                            const float* __restrict__ b1, int n) {
    __shared__ float xs[32 * 132];
    __shared__ float ws[64 * 64];
    int n0 = blockIdx.x * 128;
    for (int i = threadIdx.x; i < 4096; i += 256) ws[i] = W1[i];

    int tx = threadIdx.x & 15, ty = threadIdx.x >> 4;
    float4 bq = *(const float4*)&b1[tx * 4];
    u64 acc[4][4];
#pragma unroll
    for (int j = 0; j < 4; j++) {
        acc[j][0] = pack2(bq.x, bq.x);
        acc[j][1] = pack2(bq.y, bq.y);
        acc[j][2] = pack2(bq.z, bq.z);
        acc[j][3] = pack2(bq.w, bq.w);
    }
    const float* xrow = &xs[ty * 8];
    const float* wrow = &ws[tx * 4];

#pragma unroll
    for (int pass = 0; pass < 2; pass++) {
        __syncthreads();
        for (int i = threadIdx.x; i < 128 * 8; i += 256) {
            int node = i >> 3, cq = (i & 7) * 4;
            float4 v = make_float4(0.f, 0.f, 0.f, 0.f);
            if (n0 + node < n)
                v = *(const float4*)&x[(size_t)(n0 + node) * 64 + pass * 32 + cq];
            xs[(cq + 0) * 132 + node] = v.x;
            xs[(cq + 1) * 132 + node] = v.y;
            xs[(cq + 2) * 132 + node] = v.z;
            xs[(cq + 3) * 132 + node] = v.w;
        }
        __syncthreads();
#pragma unroll 8
        for (int dd = 0; dd < 32; dd++) {
            int d = pass * 32 + dd;
            float4 a0 = *(const float4*)&xrow[dd * 132];
            float4 a1 = *(const float4*)&xrow[dd * 132 + 4];
            float4 w  = *(const float4*)&wrow[d * 64];
            u64 p0 = pack2(a0.x, a0.y);
            u64 p1 = pack2(a0.z, a0.w);
            u64 p2 = pack2(a1.x, a1.y);
            u64 p3 = pack2(a1.z, a1.w);
            u64 w0 = pack2(w.x, w.x), w1 = pack2(w.y, w.y);
            u64 w2 = pack2(w.z, w.z), w3 = pack2(w.w, w.w);
            acc[0][0] = ffma2(p0, w0, acc[0][0]); acc[0][1] = ffma2(p0, w1, acc[0][1]);
            acc[0][2] = ffma2(p0, w2, acc[0][2]); acc[0][3] = ffma2(p0, w3, acc[0][3]);
            acc[1][0] = ffma2(p1, w0, acc[1][0]); acc[1][1] = ffma2(p1, w1, acc[1][1]);
            acc[1][2] = ffma2(p1, w2, acc[1][2]); acc[1][3] = ffma2(p1, w3, acc[1][3]);
            acc[2][0] = ffma2(p2, w0, acc[2][0]); acc[2][1] = ffma2(p2, w1, acc[2][1]);
            acc[2][2] = ffma2(p2, w2, acc[2][2]); acc[2][3] = ffma2(p2, w3, acc[2][3]);
            acc[3][0] = ffma2(p3, w0, acc[3][0]); acc[3][1] = ffma2(p3, w1, acc[3][1]);
            acc[3][2] = ffma2(p3, w2, acc[3][2]); acc[3][3] = ffma2(p3, w3, acc[3][3]);
        }
    }
    unsigned int hb;
#pragma unroll
    for (int j = 0; j < 4; j++) {
        float2 c0 = unpack2(acc[j][0]);
        float2 c1 = unpack2(acc[j][1]);
        float2 c2 = unpack2(acc[j][2]);
        float2 c3 = unpack2(acc[j][3]);
        int ne = n0 + ty * 8 + 2 * j;
        if (ne < n) {
            __half2 hA = __floats2half2_rn(c0.x, c1.x);
            __half2 hB = __floats2half2_rn(c2.x, c3.x);
            uint2 v; v.x = *(unsigned int*)&hA; v.y = *(unsigned int*)&hB;
            *(uint2*)&g_xwh[(size_t)ne * 32 + tx * 2] = v;
        }
        if (ne + 1 < n) {
            __half2 hA = __floats2half2_rn(c0.y, c1.y);
            __half2 hB = __floats2half2_rn(c2.y, c3.y);
            uint2 v; v.x = *(unsigned int*)&hA; v.y = *(unsigned int*)&hB;
            *(uint2*)&g_xwh[(size_t)(ne + 1) * 32 + tx * 2] = v;
        }
    }
    (void)hb;
}

// ---------------------------------------------------------------- fused: ppf (lane-per-edge) + segmax (lane-per-dim)
// + relu(seg @ W2 + b2); 2 nodes per warp per GEMV group. Re-zeroes g_deg at tail.
__global__ void __launch_bounds__(256) k_node_out(const float* __restrict__ W1,
                                                  const float* __restrict__ W2,
                                                  const float* __restrict__ b2,
                                                  float* __restrict__ out, int n, int E) {
    __shared__ float ws[64 * 128];
    __shared__ float sdup[8][512];   // [warp]: [0..255] results (2 nodes dup-pairs), [256..415] staging
    for (int i = threadIdx.x; i < 64 * 128; i += 256) ws[i] = W2[i];
    __syncthreads();

    int lane = threadIdx.x & 31;
    int wid  = threadIdx.x >> 5;

    float inv = (float)((double)(E + n) / g_sum);
    const float* Wp = W1 + 64 * 64;
    float2 w0 = *(const float2*)&Wp[0 * 64 + lane * 2];
    w0.x *= inv; w0.y *= inv;                   // fold dist normalization into w0
    float2 w1 = *(const float2*)&Wp[1 * 64 + lane * 2];
    float2 w2 = *(const float2*)&Wp[2 * 64 + lane * 2];
    float2 w3 = *(const float2*)&Wp[3 * 64 + lane * 2];
    float4 bq = *(const float4*)&b2[lane * 4];
    u64 bb0 = pack2(bq.x, bq.y);
    u64 bb1 = pack2(bq.z, bq.w);

    float* stage = &sdup[wid][256];

    int step = gridDim.x * 8 * 2;
    for (int base = (blockIdx.x * 8 + wid) * 2; base < n; base += step) {
        // phase 1: per node — ppf (lane=edge) then segmax (lane=dims)
#pragma unroll
        for (int k = 0; k < 2; k++) {
            int node = base + k;
            float ax = 0.f, ay = 0.f;
            if (node < n) {
                float2 xw = __half22float2(g_xwh[(size_t)node * 32 + lane]);
                ax = fmaxf(xw.x, 0.f);   // self-loop: ppf == 0 exactly
                ay = fmaxf(xw.y, 0.f);
                float4 prq = g_pn[2 * node + 0];   // uniform -> broadcast
                float4 n1q = g_pn[2 * node + 1];
                int beg = g_off[node];
                int end = g_off[node + 1];
                for (int ch = beg; ch < end; ch += 32) {
                    int i = ch + lane;
                    if (i < end) {
                        int cc = g_col[i];
                        float4 pc = g_pn[2 * cc + 0];
                        float4 n2 = g_pn[2 * cc + 1];
                        float dx = pc.x - prq.x;
                        float dy = pc.y - prq.y;
                        float dz = pc.z - prq.z;
                        float pd = dx * dx + dy * dy + dz * dz;   // raw; inv in w0
                        float q1 = ppf_angle(n1q.x, n1q.y, n1q.z, dx, dy, dz);
                        float q2 = ppf_angle(n2.x, n2.y, n2.z, dx, dy, dz);
                        float q3 = ppf_angle(n1q.x, n1q.y, n1q.z, n2.x, n2.y, n2.z);
                        *(float4*)&stage[lane * 4] = make_float4(pd, q1, q2, q3);
                        stage[128 + lane] = __int_as_float(cc);
                    }
                    __syncwarp();
                    int m = end - ch; if (m > 32) m = 32;
#pragma unroll 4
                    for (int e2 = 0; e2 < m; e2++) {
                        float4 q = *(const float4*)&stage[e2 * 4];       // broadcast LDS
                        int ce = __float_as_int(stage[128 + e2]);
                        float2 xc = __half22float2(g_xwh[(size_t)ce * 32 + lane]);
                        float hx = fmaf(q.x, w0.x, fmaf(q.y, w1.x, fmaf(q.z, w2.x, fmaf(q.w, w3.x, xc.x))));
                        float hy = fmaf(q.x, w0.y, fmaf(q.y, w1.y, fmaf(q.z, w2.y, fmaf(q.w, w3.y, xc.y))));
                        ax = fmaxf(ax, hx);
                        ay = fmaxf(ay, hy);
                    }
                    __syncwarp();
                }
            }
            *(float4*)&sdup[wid][k * 128 + lane * 4] = make_float4(ax, ax, ay, ay);
        }
        __syncwarp();

        // phase 2: GEMV for 2 nodes; direct u64 smem loads + f32x2
        u64 a0x = bb0, a0y = bb1;
        u64 a1x = bb0, a1y = bb1;
#pragma unroll 8
        for (int jp = 0; jp < 32; jp++) {
            ulonglong2 wA = *(const ulonglong2*)&ws[(2 * jp) * 128 + lane * 4];
            ulonglong2 wB = *(const ulonglong2*)&ws[(2 * jp + 1) * 128 + lane * 4];
            ulonglong2 s0 = *(const ulonglong2*)&sdup[wid][0 * 128 + jp * 4];
            ulonglong2 s1 = *(const ulonglong2*)&sdup[wid][1 * 128 + jp * 4];
            a0x = ffma2(s0.x, wA.x, a0x); a0y = ffma2(s0.x, wA.y, a0y);
            a0x = ffma2(s0.y, wB.x, a0x); a0y = ffma2(s0.y, wB.y, a0y);
            a1x = ffma2(s1.x, wA.x, a1x); a1y = ffma2(s1.x, wA.y, a1y);
            a1x = ffma2(s1.y, wB.x, a1x); a1y = ffma2(s1.y, wB.y, a1y);
        }
        __syncwarp();

        u64 rx[2] = {a0x, a1x};
        u64 ry[2] = {a0y, a1y};
#pragma unroll
        for (int k = 0; k < 2; k++) {
            int node = base + k;
            if (node < n) {
                float2 lo = unpack2(rx[k]);
                float2 hi = unpack2(ry[k]);
                float4 o = make_float4(fmaxf(lo.x, 0.f), fmaxf(lo.y, 0.f),
                                       fmaxf(hi.x, 0.f), fmaxf(hi.y, 0.f));
                *(float4*)&out[(size_t)node * 128 + lane * 4] = o;
            }
        }
    }

    // tail: re-zero g_deg for the next kernel_launch call (entry invariant)
    for (int i = blockIdx.x * 256 + threadIdx.x; i < n; i += gridDim.x * 256)
        g_deg[i] = 0;
}

// ---------------------------------------------------------------- launch (6 kernels)
extern "C" void kernel_launch(void* const* d_in, const int* in_sizes, int n_in,
                              void* d_out, int out_size) {
    const float* x   = (const float*)d_in[0];
    const float* pos = (const float*)d_in[1];
    const float* nrm = (const float*)d_in[2];
    const int*   ei  = (const int*)d_in[3];
    // d_in[4] = batch (unused)
    const float* W1  = (const float*)d_in[5];
    const float* b1  = (const float*)d_in[6];
    const float* W2  = (const float*)d_in[7];
    const float* b2  = (const float*)d_in[8];
    float* out = (float*)d_out;

    int N = in_sizes[1] / 3;
    int E = in_sizes[3] / 2;
    int nb = (N + 1023) / 1024;

    k_prep<<<(E + 255) / 256, 256>>>(ei, pos, nrm, N, E);
    k_scan1<<<nb, 256>>>(N);
    k_scan23<<<(N + 255) / 256, 256>>>(nb, N, E);
    k_scat1<<<(E + 255) / 256, 256>>>(ei, E);              // profiled slot #4
    k_xw<<<(N + 127) / 128, 256>>>(x, W1, b1, N);
    k_node_out<<<592, 256>>>(W1, W2, b2, out, N, E);
}

// round 15
// speedup vs baseline: 1.0623x; 1.0030x over previous
#include <cuda_runtime.h>
#include <cuda_fp16.h>
#include <math.h>

#define NN 100000
#define EE 1600000

// Scratch (device globals; no allocation allowed).
// INVARIANT: g_deg all-zero at every kernel_launch entry (zero-init at load;
// re-established by k_node_out tail each call). g_sum is reset in k_scan23.
__device__ __half2 g_xwh[(size_t)NN * 32];  // fp16 xw: [node][32 x half2]
__device__ int    g_col[EE];                // CSR-ordered target cols
__device__ float4 g_pn[(size_t)NN * 2];     // packed {pos,0},{nrm,0} per node
__device__ int    g_deg[NN];
__device__ int    g_off[NN + 1];
__device__ int    g_cur[NN];
__device__ int    g_bsum[128];
__device__ double g_sum;

typedef unsigned long long u64;

__device__ __forceinline__ u64 ffma2(u64 a, u64 b, u64 c) {
    u64 d;
    asm("fma.rn.f32x2 %0, %1, %2, %3;" : "=l"(d) : "l"(a), "l"(b), "l"(c));
    return d;
}
__device__ __forceinline__ u64 pack2(float lo, float hi) {
    u64 r;
    asm("mov.b64 %0, {%1, %2};" : "=l"(r) : "f"(lo), "f"(hi));
    return r;
}
__device__ __forceinline__ float2 unpack2(u64 v) {
    float lo, hi;
    asm("mov.b64 {%0, %1}, %2;" : "=f"(lo), "=f"(hi) : "l"(v));
    return make_float2(lo, hi);
}

__device__ __forceinline__ float fast_atan2p(float y, float x) {
    float ax = fabsf(x);
    float mn = fminf(y, ax);
    float mx = fmaxf(y, ax);
    float t = __fdividef(mn, fmaxf(mx, 1e-30f));
    float z = t * t;
    float p = fmaf(z, -0.01172120f, 0.05265332f);
    p = fmaf(z, p, -0.11643287f);
    p = fmaf(z, p, 0.19354346f);
    p = fmaf(z, p, -0.33262347f);
    p = fmaf(z, p, 0.99997726f);
    float a = t * p;
    a = (y > ax) ? (1.57079632679f - a) : a;
    a = (x < 0.f) ? (3.14159265359f - a) : a;
    return a;
}

__device__ __forceinline__ float ppf_angle(float ax, float ay, float az,
                                           float bx, float by, float bz) {
    float cx = ay * bz - az * by;
    float cy = az * bx - ax * bz;
    float cz = ax * by - ay * bx;
    float dot = ax * bx + ay * by + az * bz;
    float nrm = sqrtf(cx * cx + cy * cy + cz * cz);
    return fast_atan2p(nrm, dot);
}

// ---------------------------------------------------------------- prep: pack pos/nrm (e<N) + degree count (e<E)
__global__ void k_prep(const int* __restrict__ ei, const float* __restrict__ pos,
                       const float* __restrict__ nrm, int n, int E) {
    int e = blockIdx.x * 256 + threadIdx.x;
    if (e < n) {
        g_pn[2 * e + 0] = make_float4(pos[3 * e], pos[3 * e + 1], pos[3 * e + 2], 0.f);
        g_pn[2 * e + 1] = make_float4(nrm[3 * e], nrm[3 * e + 1], nrm[3 * e + 2], 0.f);
    }
    if (e < E) atomicAdd(&g_deg[ei[e]], 1);
}

// ---------------------------------------------------------------- scan stage 1
__global__ void k_scan1(int n) {
    int base = blockIdx.x * 1024 + threadIdx.x * 4;
    int d0 = 0, d1 = 0, d2 = 0, d3 = 0;
    if (base + 3 < n) {
        int4 v = *(const int4*)&g_deg[base];
        d0 = v.x; d1 = v.y; d2 = v.z; d3 = v.w;
    } else {
        if (base + 0 < n) d0 = g_deg[base + 0];
        if (base + 1 < n) d1 = g_deg[base + 1];
        if (base + 2 < n) d2 = g_deg[base + 2];
        if (base + 3 < n) d3 = g_deg[base + 3];
    }
    int s = d0 + d1 + d2 + d3;
    int lane = threadIdx.x & 31, wid = threadIdx.x >> 5;
    int v = s;
#pragma unroll
    for (int o = 1; o < 32; o <<= 1) {
        int y = __shfl_up_sync(0xffffffffu, v, o);
        if (lane >= o) v += y;
    }
    __shared__ int ws[8];
    if (lane == 31) ws[wid] = v;
    __syncthreads();
    if (threadIdx.x == 0) {
        int run = 0;
#pragma unroll
        for (int i = 0; i < 8; i++) { int t = ws[i]; ws[i] = run; run += t; }
        g_bsum[blockIdx.x] = run;
    }
    __syncthreads();
    int excl = v - s + ws[wid];
    if (base + 0 < n) g_off[base + 0] = excl;
    if (base + 1 < n) g_off[base + 1] = excl + d0;
    if (base + 2 < n) g_off[base + 2] = excl + d0 + d1;
    if (base + 3 < n) g_off[base + 3] = excl + d0 + d1 + d2;
}

// ---------------------------------------------------------------- scan stage 2+3 merged (also resets g_sum)
__global__ void k_scan23(int nb, int n, int E) {
    __shared__ int bs[128];
    __shared__ int wsum[4];
    int t = threadIdx.x;  // 256 threads
    int s = 0, v = 0;
    int lane = t & 31, w = t >> 5;
    if (t < 128) {
        s = (t < nb) ? g_bsum[t] : 0;
        v = s;
#pragma unroll
        for (int o = 1; o < 32; o <<= 1) {
            int y = __shfl_up_sync(0xffffffffu, v, o);
            if (lane >= o) v += y;
        }
        if (lane == 31) wsum[w] = v;
    }
    __syncthreads();
    if (t == 0) {
        int run = 0;
#pragma unroll
        for (int i = 0; i < 4; i++) { int x = wsum[i]; wsum[i] = run; run += x; }
    }
    __syncthreads();
    if (t < 128) bs[t] = v - s + wsum[w];
    __syncthreads();
    int i = blockIdx.x * 256 + t;
    if (i < n) {
        int o = g_off[i] + bs[i >> 10];
        g_off[i] = o;
        g_cur[i] = o;
    }
    if (i == 0) {
        g_off[n] = E;
        g_sum = 0.0;   // reset accumulator before k_scat1 adds to it
    }
}

// ---------------------------------------------------------------- col-scatter + dist sum   [profiled slot #4]
__global__ void k_scat1(const int* __restrict__ ei, int E) {
    int e = blockIdx.x * 256 + threadIdx.x;
    float dist = 0.f;
    if (e < E) {
        int r = ei[e], c = ei[E + e];
        float4 pr = g_pn[2 * r + 0];
        float4 pc = g_pn[2 * c + 0];
        float dx = pc.x - pr.x;
        float dy = pc.y - pr.y;
        float dz = pc.z - pr.z;
        dist = dx * dx + dy * dy + dz * dz;
        int p = atomicAdd(&g_cur[r], 1);
        g_col[p] = c;
    }
#pragma unroll
    for (int o = 16; o > 0; o >>= 1) dist += __shfl_down_sync(0xffffffffu, dist, o);
    __shared__ float wpart[8];
    int lane = threadIdx.x & 31, wid = threadIdx.x >> 5;
    if (lane == 0) wpart[wid] = dist;
    __syncthreads();
    if (threadIdx.x == 0) {
        float s = 0.f;
#pragma unroll
        for (int i = 0; i < 8; i++) s += wpart[i];
        atomicAdd(&g_sum, (double)s);
    }
}

// ---------------------------------------------------------------- xw = x @ W1[:64,:] + b1 (fp16 store)
__global__ void __launch_bounds__(256) k_xw(const float* __restrict__ x,
                                            const float* __restrict__ W1,
                                            const float* __restrict__ b1, int n) {
    __shared__ float xs[32 * 132];
    __shared__ float ws[64 * 64];
    int n0 = blockIdx.x * 128;
    for (int i = threadIdx.x; i < 4096; i += 256) ws[i] = W1[i];

    int tx = threadIdx.x & 15, ty = threadIdx.x >> 4;
    float4 bq = *(const float4*)&b1[tx * 4];
    u64 acc[4][4];
#pragma unroll
    for (int j = 0; j < 4; j++) {
        acc[j][0] = pack2(bq.x, bq.x);
        acc[j][1] = pack2(bq.y, bq.y);
        acc[j][2] = pack2(bq.z, bq.z);
        acc[j][3] = pack2(bq.w, bq.w);
    }
    const float* xrow = &xs[ty * 8];
    const float* wrow = &ws[tx * 4];

#pragma unroll
    for (int pass = 0; pass < 2; pass++) {
        __syncthreads();
        for (int i = threadIdx.x; i < 128 * 8; i += 256) {
            int node = i >> 3, cq = (i & 7) * 4;
            float4 v = make_float4(0.f, 0.f, 0.f, 0.f);
            if (n0 + node < n)
                v = *(const float4*)&x[(size_t)(n0 + node) * 64 + pass * 32 + cq];
            xs[(cq + 0) * 132 + node] = v.x;
            xs[(cq + 1) * 132 + node] = v.y;
            xs[(cq + 2) * 132 + node] = v.z;
            xs[(cq + 3) * 132 + node] = v.w;
        }
        __syncthreads();
#pragma unroll 8
        for (int dd = 0; dd < 32; dd++) {
            int d = pass * 32 + dd;
            float4 a0 = *(const float4*)&xrow[dd * 132];
            float4 a1 = *(const float4*)&xrow[dd * 132 + 4];
            float4 w  = *(const float4*)&wrow[d * 64];
            u64 p0 = pack2(a0.x, a0.y);
            u64 p1 = pack2(a0.z, a0.w);
            u64 p2 = pack2(a1.x, a1.y);
            u64 p3 = pack2(a1.z, a1.w);
            u64 w0 = pack2(w.x, w.x), w1 = pack2(w.y, w.y);
            u64 w2 = pack2(w.z, w.z), w3 = pack2(w.w, w.w);
            acc[0][0] = ffma2(p0, w0, acc[0][0]); acc[0][1] = ffma2(p0, w1, acc[0][1]);
            acc[0][2] = ffma2(p0, w2, acc[0][2]); acc[0][3] = ffma2(p0, w3, acc[0][3]);
            acc[1][0] = ffma2(p1, w0, acc[1][0]); acc[1][1] = ffma2(p1, w1, acc[1][1]);
            acc[1][2] = ffma2(p1, w2, acc[1][2]); acc[1][3] = ffma2(p1, w3, acc[1][3]);
            acc[2][0] = ffma2(p2, w0, acc[2][0]); acc[2][1] = ffma2(p2, w1, acc[2][1]);
            acc[2][2] = ffma2(p2, w2, acc[2][2]); acc[2][3] = ffma2(p2, w3, acc[2][3]);
            acc[3][0] = ffma2(p3, w0, acc[3][0]); acc[3][1] = ffma2(p3, w1, acc[3][1]);
            acc[3][2] = ffma2(p3, w2, acc[3][2]); acc[3][3] = ffma2(p3, w3, acc[3][3]);
        }
    }
    unsigned int hb;
#pragma unroll
    for (int j = 0; j < 4; j++) {
        float2 c0 = unpack2(acc[j][0]);
        float2 c1 = unpack2(acc[j][1]);
        float2 c2 = unpack2(acc[j][2]);
        float2 c3 = unpack2(acc[j][3]);
        int ne = n0 + ty * 8 + 2 * j;
        if (ne < n) {
            __half2 hA = __floats2half2_rn(c0.x, c1.x);
            __half2 hB = __floats2half2_rn(c2.x, c3.x);
            uint2 v; v.x = *(unsigned int*)&hA; v.y = *(unsigned int*)&hB;
            *(uint2*)&g_xwh[(size_t)ne * 32 + tx * 2] = v;
        }
        if (ne + 1 < n) {
            __half2 hA = __floats2half2_rn(c0.y, c1.y);
            __half2 hB = __floats2half2_rn(c2.y, c3.y);
            uint2 v; v.x = *(unsigned int*)&hA; v.y = *(unsigned int*)&hB;
            *(uint2*)&g_xwh[(size_t)(ne + 1) * 32 + tx * 2] = v;
        }
    }
    (void)hb;
}

// ---------------------------------------------------------------- fused: ppf (lane-per-edge) + segmax (lane-per-dim)
// + relu(seg @ W2 + b2); 2 nodes per warp per GEMV group. Re-zeroes g_deg at tail.
__global__ void __launch_bounds__(256) k_node_out(const float* __restrict__ W1,
                                                  const float* __restrict__ W2,
                                                  const float* __restrict__ b2,
                                                  float* __restrict__ out, int n, int E) {
    __shared__ float ws[64 * 128];
    __shared__ float sdup[8][512];   // [warp]: [0..255] results (2 nodes dup-pairs), [256..415] staging
    for (int i = threadIdx.x; i < 64 * 128; i += 256) ws[i] = W2[i];
    __syncthreads();

    int lane = threadIdx.x & 31;
    int wid  = threadIdx.x >> 5;

    float inv = (float)((double)(E + n) / g_sum);
    const float* Wp = W1 + 64 * 64;
    float2 w0 = *(const float2*)&Wp[0 * 64 + lane * 2];
    w0.x *= inv; w0.y *= inv;                   // fold dist normalization into w0
    float2 w1 = *(const float2*)&Wp[1 * 64 + lane * 2];
    float2 w2 = *(const float2*)&Wp[2 * 64 + lane * 2];
    float2 w3 = *(const float2*)&Wp[3 * 64 + lane * 2];
    float4 bq = *(const float4*)&b2[lane * 4];
    u64 bb0 = pack2(bq.x, bq.y);
    u64 bb1 = pack2(bq.z, bq.w);

    float* stage = &sdup[wid][256];

    int step = gridDim.x * 8 * 2;
    for (int base = (blockIdx.x * 8 + wid) * 2; base < n; base += step) {
        // phase 1: per node — ppf (lane=edge) then segmax (lane=dims)
#pragma unroll
        for (int k = 0; k < 2; k++) {
            int node = base + k;
            float ax = 0.f, ay = 0.f;
            if (node < n) {
                float2 xw = __half22float2(g_xwh[(size_t)node * 32 + lane]);
                ax = fmaxf(xw.x, 0.f);   // self-loop: ppf == 0 exactly
                ay = fmaxf(xw.y, 0.f);
                float4 prq = g_pn[2 * node + 0];   // uniform -> broadcast
                float4 n1q = g_pn[2 * node + 1];
                int beg = g_off[node];
                int end = g_off[node + 1];
                for (int ch = beg; ch < end; ch += 32) {
                    int i = ch + lane;
                    if (i < end) {
                        int cc = g_col[i];
                        float4 pc = g_pn[2 * cc + 0];
                        float4 n2 = g_pn[2 * cc + 1];
                        float dx = pc.x - prq.x;
                        float dy = pc.y - prq.y;
                        float dz = pc.z - prq.z;
                        float pd = dx * dx + dy * dy + dz * dz;   // raw; inv in w0
                        float q1 = ppf_angle(n1q.x, n1q.y, n1q.z, dx, dy, dz);
                        float q2 = ppf_angle(n2.x, n2.y, n2.z, dx, dy, dz);
                        float q3 = ppf_angle(n1q.x, n1q.y, n1q.z, n2.x, n2.y, n2.z);
                        *(float4*)&stage[lane * 4] = make_float4(pd, q1, q2, q3);
                        stage[128 + lane] = __int_as_float(cc);
                    }
                    __syncwarp();
                    int m = end - ch; if (m > 32) m = 32;
#pragma unroll 4
                    for (int e2 = 0; e2 < m; e2++) {
                        float4 q = *(const float4*)&stage[e2 * 4];       // broadcast LDS
                        int ce = __float_as_int(stage[128 + e2]);
                        float2 xc = __half22float2(g_xwh[(size_t)ce * 32 + lane]);
                        float hx = fmaf(q.x, w0.x, fmaf(q.y, w1.x, fmaf(q.z, w2.x, fmaf(q.w, w3.x, xc.x))));
                        float hy = fmaf(q.x, w0.y, fmaf(q.y, w1.y, fmaf(q.z, w2.y, fmaf(q.w, w3.y, xc.y))));
                        ax = fmaxf(ax, hx);
                        ay = fmaxf(ay, hy);
                    }
                    __syncwarp();
                }
            }
            *(float4*)&sdup[wid][k * 128 + lane * 4] = make_float4(ax, ax, ay, ay);
        }
        __syncwarp();

        // phase 2: GEMV for 2 nodes; direct u64 smem loads + f32x2
        u64 a0x = bb0, a0y = bb1;
        u64 a1x = bb0, a1y = bb1;
#pragma unroll 8
        for (int jp = 0; jp < 32; jp++) {
            ulonglong2 wA = *(const ulonglong2*)&ws[(2 * jp) * 128 + lane * 4];
            ulonglong2 wB = *(const ulonglong2*)&ws[(2 * jp + 1) * 128 + lane * 4];
            ulonglong2 s0 = *(const ulonglong2*)&sdup[wid][0 * 128 + jp * 4];
            ulonglong2 s1 = *(const ulonglong2*)&sdup[wid][1 * 128 + jp * 4];
            a0x = ffma2(s0.x, wA.x, a0x); a0y = ffma2(s0.x, wA.y, a0y);
            a0x = ffma2(s0.y, wB.x, a0x); a0y = ffma2(s0.y, wB.y, a0y);
            a1x = ffma2(s1.x, wA.x, a1x); a1y = ffma2(s1.x, wA.y, a1y);
            a1x = ffma2(s1.y, wB.x, a1x); a1y = ffma2(s1.y, wB.y, a1y);
        }
        __syncwarp();

        u64 rx[2] = {a0x, a1x};
        u64 ry[2] = {a0y, a1y};
#pragma unroll
        for (int k = 0; k < 2; k++) {
            int node = base + k;
            if (node < n) {
                float2 lo = unpack2(rx[k]);
                float2 hi = unpack2(ry[k]);
                float4 o = make_float4(fmaxf(lo.x, 0.f), fmaxf(lo.y, 0.f),
                                       fmaxf(hi.x, 0.f), fmaxf(hi.y, 0.f));
                *(float4*)&out[(size_t)node * 128 + lane * 4] = o;
            }
        }
    }

    // tail: re-zero g_deg for the next kernel_launch call (entry invariant)
    for (int i = blockIdx.x * 256 + threadIdx.x; i < n; i += gridDim.x * 256)
        g_deg[i] = 0;
}

// ---------------------------------------------------------------- launch (6 kernels)
extern "C" void kernel_launch(void* const* d_in, const int* in_sizes, int n_in,
                              void* d_out, int out_size) {
    const float* x   = (const float*)d_in[0];
    const float* pos = (const float*)d_in[1];
    const float* nrm = (const float*)d_in[2];
    const int*   ei  = (const int*)d_in[3];
    // d_in[4] = batch (unused)
    const float* W1  = (const float*)d_in[5];
    const float* b1  = (const float*)d_in[6];
    const float* W2  = (const float*)d_in[7];
    const float* b2  = (const float*)d_in[8];
    float* out = (float*)d_out;

    int N = in_sizes[1] / 3;
    int E = in_sizes[3] / 2;
    int nb = (N + 1023) / 1024;

    k_prep<<<(E + 255) / 256, 256>>>(ei, pos, nrm, N, E);
    k_scan1<<<nb, 256>>>(N);
    k_scan23<<<(N + 255) / 256, 256>>>(nb, N, E);
    k_scat1<<<(E + 255) / 256, 256>>>(ei, E);              // profiled slot #4
    k_xw<<<(N + 127) / 128, 256>>>(x, W1, b1, N);
    k_node_out<<<592, 256>>>(W1, W2, b2, out, N, E);
}

// round 16
// speedup vs baseline: 1.0657x; 1.0032x over previous
#include <cuda_runtime.h>
#include <cuda_fp16.h>
#include <math.h>

#define NN 100000
#define EE 1600000

// Scratch (device globals; no allocation allowed).
// INVARIANT: g_deg all-zero at every kernel_launch entry (zero-init at load;
// re-established by k_node_out tail each call). g_sum is reset in k_scan23.
__device__ __half2 g_xwh[(size_t)NN * 32];  // fp16 xw: [node][32 x half2]
__device__ int    g_col[EE];                // CSR-ordered target cols
__device__ float4 g_pn[(size_t)NN * 2];     // packed {pos,0},{nrm,0} per node
__device__ int    g_deg[NN];
__device__ int    g_off[NN + 1];
__device__ int    g_cur[NN];
__device__ int    g_bsum[128];
__device__ double g_sum;

typedef unsigned long long u64;

__device__ __forceinline__ u64 ffma2(u64 a, u64 b, u64 c) {
    u64 d;
    asm("fma.rn.f32x2 %0, %1, %2, %3;" : "=l"(d) : "l"(a), "l"(b), "l"(c));
    return d;
}
__device__ __forceinline__ u64 pack2(float lo, float hi) {
    u64 r;
    asm("mov.b64 %0, {%1, %2};" : "=l"(r) : "f"(lo), "f"(hi));
    return r;
}
__device__ __forceinline__ float2 unpack2(u64 v) {
    float lo, hi;
    asm("mov.b64 {%0, %1}, %2;" : "=f"(lo), "=f"(hi) : "l"(v));
    return make_float2(lo, hi);
}

__device__ __forceinline__ float fast_atan2p(float y, float x) {
    float ax = fabsf(x);
    float mn = fminf(y, ax);
    float mx = fmaxf(y, ax);
    float t = __fdividef(mn, fmaxf(mx, 1e-30f));
    float z = t * t;
    float p = fmaf(z, -0.01172120f, 0.05265332f);
    p = fmaf(z, p, -0.11643287f);
    p = fmaf(z, p, 0.19354346f);
    p = fmaf(z, p, -0.33262347f);
    p = fmaf(z, p, 0.99997726f);
    float a = t * p;
    a = (y > ax) ? (1.57079632679f - a) : a;
    a = (x < 0.f) ? (3.14159265359f - a) : a;
    return a;
}

__device__ __forceinline__ float ppf_angle(float ax, float ay, float az,
                                           float bx, float by, float bz) {
    float cx = ay * bz - az * by;
    float cy = az * bx - ax * bz;
    float cz = ax * by - ay * bx;
    float dot = ax * bx + ay * by + az * bz;
    float nrm = sqrtf(cx * cx + cy * cy + cz * cz);
    return fast_atan2p(nrm, dot);
}

// ---------------------------------------------------------------- prep: pack pos/nrm (e<N) + degree count (e<E)
__global__ void k_prep(const int* __restrict__ ei, const float* __restrict__ pos,
                       const float* __restrict__ nrm, int n, int E) {
    int e = blockIdx.x * 256 + threadIdx.x;
    if (e < n) {
        g_pn[2 * e + 0] = make_float4(pos[3 * e], pos[3 * e + 1], pos[3 * e + 2], 0.f);
        g_pn[2 * e + 1] = make_float4(nrm[3 * e], nrm[3 * e + 1], nrm[3 * e + 2], 0.f);
    }
    if (e < E) atomicAdd(&g_deg[ei[e]], 1);
}

// ---------------------------------------------------------------- scan stage 1
__global__ void k_scan1(int n) {
    int base = blockIdx.x * 1024 + threadIdx.x * 4;
    int d0 = 0, d1 = 0, d2 = 0, d3 = 0;
    if (base + 3 < n) {
        int4 v = *(const int4*)&g_deg[base];
        d0 = v.x; d1 = v.y; d2 = v.z; d3 = v.w;
    } else {
        if (base + 0 < n) d0 = g_deg[base + 0];
        if (base + 1 < n) d1 = g_deg[base + 1];
        if (base + 2 < n) d2 = g_deg[base + 2];
        if (base + 3 < n) d3 = g_deg[base + 3];
    }
    int s = d0 + d1 + d2 + d3;
    int lane = threadIdx.x & 31, wid = threadIdx.x >> 5;
    int v = s;
#pragma unroll
    for (int o = 1; o < 32; o <<= 1) {
        int y = __shfl_up_sync(0xffffffffu, v, o);
        if (lane >= o) v += y;
    }
    __shared__ int ws[8];
    if (lane == 31) ws[wid] = v;
    __syncthreads();
    if (threadIdx.x == 0) {
        int run = 0;
#pragma unroll
        for (int i = 0; i < 8; i++) { int t = ws[i]; ws[i] = run; run += t; }
        g_bsum[blockIdx.x] = run;
    }
    __syncthreads();
    int excl = v - s + ws[wid];
    if (base + 0 < n) g_off[base + 0] = excl;
    if (base + 1 < n) g_off[base + 1] = excl + d0;
    if (base + 2 < n) g_off[base + 2] = excl + d0 + d1;
    if (base + 3 < n) g_off[base + 3] = excl + d0 + d1 + d2;
}

// ---------------------------------------------------------------- scan stage 2+3 merged (also resets g_sum)
__global__ void k_scan23(int nb, int n, int E) {
    __shared__ int bs[128];
    __shared__ int wsum[4];
    int t = threadIdx.x;  // 256 threads
    int s = 0, v = 0;
    int lane = t & 31, w = t >> 5;
    if (t < 128) {
        s = (t < nb) ? g_bsum[t] : 0;
        v = s;
#pragma unroll
        for (int o = 1; o < 32; o <<= 1) {
            int y = __shfl_up_sync(0xffffffffu, v, o);
            if (lane >= o) v += y;
        }
        if (lane == 31) wsum[w] = v;
    }
    __syncthreads();
    if (t == 0) {
        int run = 0;
#pragma unroll
        for (int i = 0; i < 4; i++) { int x = wsum[i]; wsum[i] = run; run += x; }
    }
    __syncthreads();
    if (t < 128) bs[t] = v - s + wsum[w];
    __syncthreads();
    int i = blockIdx.x * 256 + t;
    if (i < n) {
        int o = g_off[i] + bs[i >> 10];
        g_off[i] = o;
        g_cur[i] = o;
    }
    if (i == 0) {
        g_off[n] = E;
        g_sum = 0.0;   // reset accumulator before k_scat1 adds to it
    }
}

// ---------------------------------------------------------------- col-scatter + dist sum   [profiled slot #4]
__global__ void k_scat1(const int* __restrict__ ei, int E) {
    int e = blockIdx.x * 256 + threadIdx.x;
    float dist = 0.f;
    if (e < E) {
        int r = ei[e], c = ei[E + e];
        float4 pr = g_pn[2 * r + 0];
        float4 pc = g_pn[2 * c + 0];
        float dx = pc.x - pr.x;
        float dy = pc.y - pr.y;
        float dz = pc.z - pr.z;
        dist = dx * dx + dy * dy + dz * dz;
        int p = atomicAdd(&g_cur[r], 1);
        g_col[p] = c;
    }
#pragma unroll
    for (int o = 16; o > 0; o >>= 1) dist += __shfl_down_sync(0xffffffffu, dist, o);
    __shared__ float wpart[8];
    int lane = threadIdx.x & 31, wid = threadIdx.x >> 5;
    if (lane == 0) wpart[wid] = dist;
    __syncthreads();
    if (threadIdx.x == 0) {
        float s = 0.f;
#pragma unroll
        for (int i = 0; i < 8; i++) s += wpart[i];
        atomicAdd(&g_sum, (double)s);
    }
}

// ---------------------------------------------------------------- xw = x @ W1[:64,:] + b1 (fp16 store)
__global__ void __launch_bounds__(256) k_xw(const float* __restrict__ x,
                                            const float* __restrict__ W1,
                                            const float* __restrict__ b1, int n) {
    __shared__ float xs[32 * 132];
    __shared__ float ws[64 * 64];
    int n0 = blockIdx.x * 128;
    for (int i = threadIdx.x; i < 4096; i += 256) ws[i] = W1[i];

    int tx = threadIdx.x & 15, ty = threadIdx.x >> 4;
    float4 bq = *(const float4*)&b1[tx * 4];
    u64 acc[4][4];
#pragma unroll
    for (int j = 0; j < 4; j++) {
        acc[j][0] = pack2(bq.x, bq.x);
        acc[j][1] = pack2(bq.y, bq.y);
        acc[j][2] = pack2(bq.z, bq.z);
        acc[j][3] = pack2(bq.w, bq.w);
    }
    const float* xrow = &xs[ty * 8];
    const float* wrow = &ws[tx * 4];

#pragma unroll
    for (int pass = 0; pass < 2; pass++) {
        __syncthreads();
        for (int i = threadIdx.x; i < 128 * 8; i += 256) {
            int node = i >> 3, cq = (i & 7) * 4;
            float4 v = make_float4(0.f, 0.f, 0.f, 0.f);
            if (n0 + node < n)
                v = *(const float4*)&x[(size_t)(n0 + node) * 64 + pass * 32 + cq];
            xs[(cq + 0) * 132 + node] = v.x;
            xs[(cq + 1) * 132 + node] = v.y;
            xs[(cq + 2) * 132 + node] = v.z;
            xs[(cq + 3) * 132 + node] = v.w;
        }
        __syncthreads();
#pragma unroll 8
        for (int dd = 0; dd < 32; dd++) {
            int d = pass * 32 + dd;
            float4 a0 = *(const float4*)&xrow[dd * 132];
            float4 a1 = *(const float4*)&xrow[dd * 132 + 4];
            float4 w  = *(const float4*)&wrow[d * 64];
            u64 p0 = pack2(a0.x, a0.y);
            u64 p1 = pack2(a0.z, a0.w);
            u64 p2 = pack2(a1.x, a1.y);
            u64 p3 = pack2(a1.z, a1.w);
            u64 w0 = pack2(w.x, w.x), w1 = pack2(w.y, w.y);
            u64 w2 = pack2(w.z, w.z), w3 = pack2(w.w, w.w);
            acc[0][0] = ffma2(p0, w0, acc[0][0]); acc[0][1] = ffma2(p0, w1, acc[0][1]);
            acc[0][2] = ffma2(p0, w2, acc[0][2]); acc[0][3] = ffma2(p0, w3, acc[0][3]);
            acc[1][0] = ffma2(p1, w0, acc[1][0]); acc[1][1] = ffma2(p1, w1, acc[1][1]);
            acc[1][2] = ffma2(p1, w2, acc[1][2]); acc[1][3] = ffma2(p1, w3, acc[1][3]);
            acc[2][0] = ffma2(p2, w0, acc[2][0]); acc[2][1] = ffma2(p2, w1, acc[2][1]);
            acc[2][2] = ffma2(p2, w2, acc[2][2]); acc[2][3] = ffma2(p2, w3, acc[2][3]);
            acc[3][0] = ffma2(p3, w0, acc[3][0]); acc[3][1] = ffma2(p3, w1, acc[3][1]);
            acc[3][2] = ffma2(p3, w2, acc[3][2]); acc[3][3] = ffma2(p3, w3, acc[3][3]);
        }
    }
#pragma unroll
    for (int j = 0; j < 4; j++) {
        float2 c0 = unpack2(acc[j][0]);
        float2 c1 = unpack2(acc[j][1]);
        float2 c2 = unpack2(acc[j][2]);
        float2 c3 = unpack2(acc[j][3]);
        int ne = n0 + ty * 8 + 2 * j;
        if (ne < n) {
            __half2 hA = __floats2half2_rn(c0.x, c1.x);
            __half2 hB = __floats2half2_rn(c2.x, c3.x);
            uint2 v; v.x = *(unsigned int*)&hA; v.y = *(unsigned int*)&hB;
            *(uint2*)&g_xwh[(size_t)ne * 32 + tx * 2] = v;
        }
        if (ne + 1 < n) {
            __half2 hA = __floats2half2_rn(c0.y, c1.y);
            __half2 hB = __floats2half2_rn(c2.y, c3.y);
            uint2 v; v.x = *(unsigned int*)&hA; v.y = *(unsigned int*)&hB;
            *(uint2*)&g_xwh[(size_t)(ne + 1) * 32 + tx * 2] = v;
        }
    }
}

// ---------------------------------------------------------------- fused: ppf (lane-per-edge) + segmax (lane-per-dim, xc gathers batched x4)
// + relu(seg @ W2 + b2); 2 nodes per warp per GEMV group. Re-zeroes g_deg at tail.
__global__ void __launch_bounds__(256) k_node_out(const float* __restrict__ W1,
                                                  const float* __restrict__ W2,
                                                  const float* __restrict__ b2,
                                                  float* __restrict__ out, int n, int E) {
    __shared__ float ws[64 * 128];
    __shared__ float sdup[8][512];   // [warp]: [0..255] results (2 nodes dup-pairs), [256..415] staging
    for (int i = threadIdx.x; i < 64 * 128; i += 256) ws[i] = W2[i];
    __syncthreads();

    int lane = threadIdx.x & 31;
    int wid  = threadIdx.x >> 5;

    float inv = (float)((double)(E + n) / g_sum);
    const float* Wp = W1 + 64 * 64;
    float2 w0 = *(const float2*)&Wp[0 * 64 + lane * 2];
    w0.x *= inv; w0.y *= inv;                   // fold dist normalization into w0
    float2 w1 = *(const float2*)&Wp[1 * 64 + lane * 2];
    float2 w2 = *(const float2*)&Wp[2 * 64 + lane * 2];
    float2 w3 = *(const float2*)&Wp[3 * 64 + lane * 2];
    float4 bq = *(const float4*)&b2[lane * 4];
    u64 bb0 = pack2(bq.x, bq.y);
    u64 bb1 = pack2(bq.z, bq.w);

    float* stage = &sdup[wid][256];

    int step = gridDim.x * 8 * 2;
    for (int base = (blockIdx.x * 8 + wid) * 2; base < n; base += step) {
        // phase 1: per node — ppf (lane=edge) then segmax (lane=dims)
#pragma unroll
        for (int k = 0; k < 2; k++) {
            int node = base + k;
            float ax = 0.f, ay = 0.f;
            if (node < n) {
                float2 xw = __half22float2(g_xwh[(size_t)node * 32 + lane]);
                ax = fmaxf(xw.x, 0.f);   // self-loop: ppf == 0 exactly
                ay = fmaxf(xw.y, 0.f);
                float4 prq = g_pn[2 * node + 0];   // uniform -> broadcast
                float4 n1q = g_pn[2 * node + 1];
                int beg = g_off[node];
                int end = g_off[node + 1];
                for (int ch = beg; ch < end; ch += 32) {
                    int i = ch + lane;
                    if (i < end) {
                        int cc = g_col[i];
                        float4 pc = g_pn[2 * cc + 0];
                        float4 n2 = g_pn[2 * cc + 1];
                        float dx = pc.x - prq.x;
                        float dy = pc.y - prq.y;
                        float dz = pc.z - prq.z;
                        float pd = dx * dx + dy * dy + dz * dz;   // raw; inv in w0
                        float q1 = ppf_angle(n1q.x, n1q.y, n1q.z, dx, dy, dz);
                        float q2 = ppf_angle(n2.x, n2.y, n2.z, dx, dy, dz);
                        float q3 = ppf_angle(n1q.x, n1q.y, n1q.z, n2.x, n2.y, n2.z);
                        *(float4*)&stage[lane * 4] = make_float4(pd, q1, q2, q3);
                        stage[128 + lane] = __int_as_float(cc);
                    }
                    __syncwarp();
                    int m = end - ch; if (m > 32) m = 32;
                    int e2 = 0;
                    // xc gathers batched x4: 4 independent LDGs in flight per group
                    for (; e2 + 3 < m; e2 += 4) {
                        int c0 = __float_as_int(stage[128 + e2 + 0]);
                        int c1 = __float_as_int(stage[128 + e2 + 1]);
                        int c2 = __float_as_int(stage[128 + e2 + 2]);
                        int c3 = __float_as_int(stage[128 + e2 + 3]);
                        float2 xc0 = __half22float2(g_xwh[(size_t)c0 * 32 + lane]);
                        float2 xc1 = __half22float2(g_xwh[(size_t)c1 * 32 + lane]);
                        float2 xc2 = __half22float2(g_xwh[(size_t)c2 * 32 + lane]);
                        float2 xc3 = __half22float2(g_xwh[(size_t)c3 * 32 + lane]);
                        float4 q0 = *(const float4*)&stage[(e2 + 0) * 4];
                        float4 q1 = *(const float4*)&stage[(e2 + 1) * 4];
                        float4 q2 = *(const float4*)&stage[(e2 + 2) * 4];
                        float4 q3 = *(const float4*)&stage[(e2 + 3) * 4];
                        float hx0 = fmaf(q0.x, w0.x, fmaf(q0.y, w1.x, fmaf(q0.z, w2.x, fmaf(q0.w, w3.x, xc0.x))));
                        float hy0 = fmaf(q0.x, w0.y, fmaf(q0.y, w1.y, fmaf(q0.z, w2.y, fmaf(q0.w, w3.y, xc0.y))));
                        float hx1 = fmaf(q1.x, w0.x, fmaf(q1.y, w1.x, fmaf(q1.z, w2.x, fmaf(q1.w, w3.x, xc1.x))));
                        float hy1 = fmaf(q1.x, w0.y, fmaf(q1.y, w1.y, fmaf(q1.z, w2.y, fmaf(q1.w, w3.y, xc1.y))));
                        float hx2 = fmaf(q2.x, w0.x, fmaf(q2.y, w1.x, fmaf(q2.z, w2.x, fmaf(q2.w, w3.x, xc2.x))));
                        float hy2 = fmaf(q2.x, w0.y, fmaf(q2.y, w1.y, fmaf(q2.z, w2.y, fmaf(q2.w, w3.y, xc2.y))));
                        float hx3 = fmaf(q3.x, w0.x, fmaf(q3.y, w1.x, fmaf(q3.z, w2.x, fmaf(q3.w, w3.x, xc3.x))));
                        float hy3 = fmaf(q3.x, w0.y, fmaf(q3.y, w1.y, fmaf(q3.z, w2.y, fmaf(q3.w, w3.y, xc3.y))));
                        ax = fmaxf(ax, fmaxf(fmaxf(hx0, hx1), fmaxf(hx2, hx3)));
                        ay = fmaxf(ay, fmaxf(fmaxf(hy0, hy1), fmaxf(hy2, hy3)));
                    }
                    for (; e2 < m; e2++) {
                        int ce = __float_as_int(stage[128 + e2]);
                        float2 xc = __half22float2(g_xwh[(size_t)ce * 32 + lane]);
                        float4 q = *(const float4*)&stage[e2 * 4];
                        float hx = fmaf(q.x, w0.x, fmaf(q.y, w1.x, fmaf(q.z, w2.x, fmaf(q.w, w3.x, xc.x))));
                        float hy = fmaf(q.x, w0.y, fmaf(q.y, w1.y, fmaf(q.z, w2.y, fmaf(q.w, w3.y, xc.y))));
                        ax = fmaxf(ax, hx);
                        ay = fmaxf(ay, hy);
                    }
                    __syncwarp();
                }
            }
            *(float4*)&sdup[wid][k * 128 + lane * 4] = make_float4(ax, ax, ay, ay);
        }
        __syncwarp();

        // phase 2: GEMV for 2 nodes; direct u64 smem loads + f32x2
        u64 a0x = bb0, a0y = bb1;
        u64 a1x = bb0, a1y = bb1;
#pragma unroll 8
        for (int jp = 0; jp < 32; jp++) {
            ulonglong2 wA = *(const ulonglong2*)&ws[(2 * jp) * 128 + lane * 4];
            ulonglong2 wB = *(const ulonglong2*)&ws[(2 * jp + 1) * 128 + lane * 4];
            ulonglong2 s0 = *(const ulonglong2*)&sdup[wid][0 * 128 + jp * 4];
            ulonglong2 s1 = *(const ulonglong2*)&sdup[wid][1 * 128 + jp * 4];
            a0x = ffma2(s0.x, wA.x, a0x); a0y = ffma2(s0.x, wA.y, a0y);
            a0x = ffma2(s0.y, wB.x, a0x); a0y = ffma2(s0.y, wB.y, a0y);
            a1x = ffma2(s1.x, wA.x, a1x); a1y = ffma2(s1.x, wA.y, a1y);
            a1x = ffma2(s1.y, wB.x, a1x); a1y = ffma2(s1.y, wB.y, a1y);
        }
        __syncwarp();

        u64 rx[2] = {a0x, a1x};
        u64 ry[2] = {a0y, a1y};
#pragma unroll
        for (int k = 0; k < 2; k++) {
            int node = base + k;
            if (node < n) {
                float2 lo = unpack2(rx[k]);
                float2 hi = unpack2(ry[k]);
                float4 o = make_float4(fmaxf(lo.x, 0.f), fmaxf(lo.y, 0.f),
                                       fmaxf(hi.x, 0.f), fmaxf(hi.y, 0.f));
                *(float4*)&out[(size_t)node * 128 + lane * 4] = o;
            }
        }
    }

    // tail: re-zero g_deg for the next kernel_launch call (entry invariant)
    for (int i = blockIdx.x * 256 + threadIdx.x; i < n; i += gridDim.x * 256)
        g_deg[i] = 0;
}

// ---------------------------------------------------------------- launch (6 kernels)
extern "C" void kernel_launch(void* const* d_in, const int* in_sizes, int n_in,
                              void* d_out, int out_size) {
    const float* x   = (const float*)d_in[0];
    const float* pos = (const float*)d_in[1];
    const float* nrm = (const float*)d_in[2];
    const int*   ei  = (const int*)d_in[3];
    // d_in[4] = batch (unused)
    const float* W1  = (const float*)d_in[5];
    const float* b1  = (const float*)d_in[6];
    const float* W2  = (const float*)d_in[7];
    const float* b2  = (const float*)d_in[8];
    float* out = (float*)d_out;

    int N = in_sizes[1] / 3;
    int E = in_sizes[3] / 2;
    int nb = (N + 1023) / 1024;

    k_prep<<<(E + 255) / 256, 256>>>(ei, pos, nrm, N, E);
    k_scan1<<<nb, 256>>>(N);
    k_scan23<<<(N + 255) / 256, 256>>>(nb, N, E);
    k_scat1<<<(E + 255) / 256, 256>>>(ei, E);              // profiled slot #4
    k_xw<<<(N + 127) / 128, 256>>>(x, W1, b1, N);
    k_node_out<<<592, 256>>>(W1, W2, b2, out, N, E);
}